// round 8
// baseline (speedup 1.0000x reference)
#include <cuda_runtime.h>
#include <cuda_bf16.h>
#include <cstdint>
#include <math.h>

// Problem constants
#define Bz 4
#define Sz 2048
#define Dz 2048
#define NHz 16
#define DHz 128

#define TOT (4UL*2048UL*2048UL)   // B*S*D elements

typedef unsigned long long ull;

// Scratch (allocation-free rule: __device__ globals)
__device__ float g_Q[TOT];
__device__ float g_K[TOT];
__device__ float g_V[TOT];
__device__ float g_A[TOT];
__device__ float g_R[TOT];

// ===========================================================================
// f32x2 packed-math helpers (PTX ISA 8.6+, base family sm_100/sm_103)
// ===========================================================================
__device__ __forceinline__ ull pack2(float x, float y) {
    ull r;
    asm("mov.b64 %0, {%1, %2};" : "=l"(r)
        : "r"(__float_as_uint(x)), "r"(__float_as_uint(y)));
    return r;
}
__device__ __forceinline__ float2 unpack2(ull v) {
    uint32_t lo, hi;
    asm("mov.b64 {%0, %1}, %2;" : "=r"(lo), "=r"(hi) : "l"(v));
    return make_float2(__uint_as_float(lo), __uint_as_float(hi));
}
__device__ __forceinline__ ull fma2(ull a, ull b, ull c) {
    ull d;
    asm("fma.rn.f32x2 %0, %1, %2, %3;" : "=l"(d) : "l"(a), "l"(b), "l"(c));
    return d;
}
__device__ __forceinline__ ull mul2(ull a, ull b) {
    ull d;
    asm("mul.rn.f32x2 %0, %1, %2;" : "=l"(d) : "l"(a), "l"(b));
    return d;
}

// ===========================================================================
// GEMM: C[M,N] = A[M,K] @ B[K,N] (+ Res).  128x128 tile, 8x8 per thread,
// accumulators packed as f32x2 along N (FFMA2: 2x fp32 rate).
// ===========================================================================
__global__ __launch_bounds__(256, 2) void gemm128(
    const float* __restrict__ A, const float* __restrict__ B,
    const float* __restrict__ Res, float* __restrict__ C,
    int M, int N, int K)
{
    __shared__ float sA[128][16];
    __shared__ float sB[16][136];   // padded stride (544B rows, 16B aligned)

    const int tid = threadIdx.x;
    const int tx = tid & 15, ty = tid >> 4;
    const int m0 = blockIdx.y * 128, n0 = blockIdx.x * 128;

    ull acc2[8][4];
#pragma unroll
    for (int i = 0; i < 8; i++)
#pragma unroll
        for (int j = 0; j < 4; j++) acc2[i][j] = 0ull;

    for (int k0 = 0; k0 < K; k0 += 16) {
#pragma unroll
        for (int r = 0; r < 8; r++) {
            int e = r * 256 + tid;
            int row = e >> 4, col = e & 15;
            sA[row][col] = A[(long)(m0 + row) * K + k0 + col];
        }
#pragma unroll
        for (int r = 0; r < 8; r++) {
            int e = r * 256 + tid;
            int row = e >> 7, col = e & 127;
            sB[row][col] = B[(long)(k0 + row) * N + n0 + col];
        }
        __syncthreads();
#pragma unroll
        for (int kk = 0; kk < 16; kk++) {
            const ull* bp = (const ull*)&sB[kk][tx * 8];
            ull b2[4];
            b2[0] = bp[0]; b2[1] = bp[1]; b2[2] = bp[2]; b2[3] = bp[3];
            float a[8];
#pragma unroll
            for (int i = 0; i < 8; i++) a[i] = sA[ty * 8 + i][kk];
#pragma unroll
            for (int i = 0; i < 8; i++) {
                ull a2 = pack2(a[i], a[i]);
#pragma unroll
                for (int j = 0; j < 4; j++)
                    acc2[i][j] = fma2(a2, b2[j], acc2[i][j]);
            }
        }
        __syncthreads();
    }

#pragma unroll
    for (int i = 0; i < 8; i++) {
        long row = m0 + ty * 8 + i;
        long base = row * N + n0 + tx * 8;
#pragma unroll
        for (int j = 0; j < 4; j++) {
            float2 v = unpack2(acc2[i][j]);
            if (Res) {
                float2 rr = *(const float2*)&Res[base + 2 * j];
                v.x += rr.x; v.y += rr.y;
            }
            *(float2*)&C[base + 2 * j] = v;
        }
    }
}

// ---------------------------------------------------------------------------
// RoPE: in-place on (B,S,NH*128) with interleaved pairs per head
// ---------------------------------------------------------------------------
__global__ void rope_kernel(float* __restrict__ X,
                            const float* __restrict__ cosb,
                            const float* __restrict__ sinb)
{
    int idx = blockIdx.x * blockDim.x + threadIdx.x;
    int i = idx & 63;
    int h = (idx >> 6) & 15;
    int s = (idx >> 10) & 2047;
    int b = idx >> 21;
    long base = ((long)(b * Sz + s)) * Dz + h * DHz + 2 * i;
    float c = cosb[s * 64 + i], sn = sinb[s * 64 + i];
    float x1 = X[base], x2 = X[base + 1];
    X[base]     = x1 * c - x2 * sn;
    X[base + 1] = x1 * sn + x2 * c;
}

// ---------------------------------------------------------------------------
// Flash attention with f32x2 math.
//   sQd : Q duplicated per element {q,q}   [64 rows][128 k]   (ull)
//   sS2 : P duplicated per element {p,p}   [64 rows][64 kc]   (ull)
//   sKT : K transposed                      [128 k][66 keys]  (float)
//   sV  : V                                 [64 rows][128 c]  (float)
// mask int32: nonzero == masked.
// ---------------------------------------------------------------------------
#define FLQ_OFF  0
#define FLS_OFF  65536
#define FLK_OFF  98304
#define FLV_OFF  132096
#define FL_SMEM  164864

__global__ __launch_bounds__(256) void flash_kernel(
    const float* __restrict__ Q, const float* __restrict__ K,
    const float* __restrict__ V, const int* __restrict__ mask,
    float* __restrict__ O)
{
    extern __shared__ char smc[];
    ull*   sQd = (ull*)(smc + FLQ_OFF);
    ull*   sS2 = (ull*)(smc + FLS_OFF);
    float* sKT = (float*)(smc + FLK_OFF);
    float* sV  = (float*)(smc + FLV_OFF);

    const int tid = threadIdx.x;
    const int tx = tid & 15, ty = tid >> 4;
    const int blk = blockIdx.x;
    const int qt = blk & 31;
    const int h  = (blk >> 5) & 15;
    const int b  = blk >> 9;
    const int q0 = qt * 64;
    const float scale = 0.08838834764831845f;   // 1/sqrt(128)

    // load Q tile, duplicated
#pragma unroll
    for (int r = 0; r < 32; r++) {
        int e = r * 256 + tid;
        int row = e >> 7, col = e & 127;
        float q = Q[((long)(b * Sz + q0 + row)) * Dz + h * DHz + col];
        sQd[row * 128 + col] = pack2(q, q);
    }

    float m_i[4], l_i[4];
    ull o2[4][4];
#pragma unroll
    for (int i = 0; i < 4; i++) {
        m_i[i] = -1e30f; l_i[i] = 0.f;
#pragma unroll
        for (int c = 0; c < 4; c++) o2[i][c] = 0ull;
    }

    const int* mrow = mask + (long)b * Sz;

    for (int k0 = 0; k0 < Sz; k0 += 64) {
        __syncthreads();   // protect sKT/sV/sS2 from previous iteration
#pragma unroll
        for (int r = 0; r < 32; r++) {
            int e = r * 256 + tid;
            int row = e >> 7, col = e & 127;
            long gg = ((long)(b * Sz + k0 + row)) * Dz + h * DHz + col;
            sKT[col * 66 + row] = K[gg];     // transposed
            sV[row * 128 + col] = V[gg];
        }
        __syncthreads();

        // scores: acc2[i][j2] covers keys tx*4 + {2*j2, 2*j2+1}
        ull acc2[4][2];
#pragma unroll
        for (int i = 0; i < 4; i++) { acc2[i][0] = 0ull; acc2[i][1] = 0ull; }

#pragma unroll 4
        for (int k = 0; k < 128; k++) {
            ull b20 = *(const ull*)&sKT[k * 66 + tx * 4];
            ull b21 = *(const ull*)&sKT[k * 66 + tx * 4 + 2];
#pragma unroll
            for (int i = 0; i < 4; i++) {
                ull a2 = sQd[(ty * 4 + i) * 128 + k];
                acc2[i][0] = fma2(a2, b20, acc2[i][0]);
                acc2[i][1] = fma2(a2, b21, acc2[i][1]);
            }
        }

        // unpack, mask + scale
        float sv[4][4];
        bool msk[4];
#pragma unroll
        for (int j = 0; j < 4; j++) msk[j] = mrow[k0 + tx * 4 + j] != 0;
#pragma unroll
        for (int i = 0; i < 4; i++) {
            float2 p0 = unpack2(acc2[i][0]);
            float2 p1 = unpack2(acc2[i][1]);
            sv[i][0] = msk[0] ? -1e30f : p0.x * scale;
            sv[i][1] = msk[1] ? -1e30f : p0.y * scale;
            sv[i][2] = msk[2] ? -1e30f : p1.x * scale;
            sv[i][3] = msk[3] ? -1e30f : p1.y * scale;
        }

        // online softmax per row (rows of a given ty live in one 16-lane half)
#pragma unroll
        for (int i = 0; i < 4; i++) {
            float tm = fmaxf(fmaxf(sv[i][0], sv[i][1]), fmaxf(sv[i][2], sv[i][3]));
#pragma unroll
            for (int d = 1; d < 16; d <<= 1)
                tm = fmaxf(tm, __shfl_xor_sync(0xffffffffu, tm, d));
            float nm = fmaxf(m_i[i], tm);
            float corr = __expf(m_i[i] - nm);
            float p[4], ps = 0.f;
#pragma unroll
            for (int j = 0; j < 4; j++) { p[j] = __expf(sv[i][j] - nm); ps += p[j]; }
#pragma unroll
            for (int d = 1; d < 16; d <<= 1)
                ps += __shfl_xor_sync(0xffffffffu, ps, d);
            l_i[i] = l_i[i] * corr + ps;
            m_i[i] = nm;
            ull corr2 = pack2(corr, corr);
#pragma unroll
            for (int c = 0; c < 4; c++) o2[i][c] = mul2(o2[i][c], corr2);
#pragma unroll
            for (int j = 0; j < 4; j++)
                sS2[(ty * 4 + i) * 64 + tx * 4 + j] = pack2(p[j], p[j]);
        }
        __syncthreads();

        // O += P @ V  (thread covers rows ty*4.., cols tx*8..; f32x2 on col pairs)
#pragma unroll 4
        for (int kc = 0; kc < 64; kc++) {
            const ull* vp = (const ull*)&sV[kc * 128 + tx * 8];
            ull v20 = vp[0], v21 = vp[1], v22 = vp[2], v23 = vp[3];
#pragma unroll
            for (int i = 0; i < 4; i++) {
                ull s2 = sS2[(ty * 4 + i) * 64 + kc];
                o2[i][0] = fma2(s2, v20, o2[i][0]);
                o2[i][1] = fma2(s2, v21, o2[i][1]);
                o2[i][2] = fma2(s2, v22, o2[i][2]);
                o2[i][3] = fma2(s2, v23, o2[i][3]);
            }
        }
    }

    // epilogue: normalize and store
#pragma unroll
    for (int i = 0; i < 4; i++) {
        float inv = 1.f / l_i[i];
        long base = ((long)(b * Sz + q0 + ty * 4 + i)) * Dz + h * DHz + tx * 8;
        float2 e0 = unpack2(o2[i][0]);
        float2 e1 = unpack2(o2[i][1]);
        float2 e2 = unpack2(o2[i][2]);
        float2 e3 = unpack2(o2[i][3]);
        float4 r0 = { e0.x * inv, e0.y * inv, e1.x * inv, e1.y * inv };
        float4 r1 = { e2.x * inv, e2.y * inv, e3.x * inv, e3.y * inv };
        *(float4*)&O[base]     = r0;
        *(float4*)&O[base + 4] = r1;
    }
}

// ---------------------------------------------------------------------------
// LayerNorm over last dim (2048), one CTA per row
// ---------------------------------------------------------------------------
__global__ __launch_bounds__(256) void ln_kernel(
    const float* __restrict__ X, const float* __restrict__ gamma,
    const float* __restrict__ beta, float* __restrict__ Y)
{
    const int row = blockIdx.x;
    const int tid = threadIdx.x;
    const float* x = X + (long)row * Dz;

    float v[8], s = 0.f, s2 = 0.f;
#pragma unroll
    for (int r = 0; r < 8; r++) {
        float t = x[r * 256 + tid];
        v[r] = t; s += t; s2 += t * t;
    }
#pragma unroll
    for (int d = 16; d >= 1; d >>= 1) {
        s  += __shfl_xor_sync(0xffffffffu, s,  d);
        s2 += __shfl_xor_sync(0xffffffffu, s2, d);
    }
    __shared__ float rs[8], rs2[8];
    __shared__ float s_mean, s_rstd;
    int wid = tid >> 5, lane = tid & 31;
    if (lane == 0) { rs[wid] = s; rs2[wid] = s2; }
    __syncthreads();
    if (tid == 0) {
        float S = 0.f, S2 = 0.f;
        for (int w = 0; w < 8; w++) { S += rs[w]; S2 += rs2[w]; }
        float mu = S * (1.f / 2048.f);
        float var = S2 * (1.f / 2048.f) - mu * mu;
        s_mean = mu;
        s_rstd = rsqrtf(var + 1e-5f);
    }
    __syncthreads();
    float mu = s_mean, rstd = s_rstd;
    float* y = Y + (long)row * Dz;
#pragma unroll
    for (int r = 0; r < 8; r++) {
        int c = r * 256 + tid;
        y[c] = (v[r] - mu) * rstd * gamma[c] + beta[c];
    }
}

// ---------------------------------------------------------------------------
extern "C" void kernel_launch(void* const* d_in, const int* in_sizes, int n_in,
                              void* d_out, int out_size)
{
    const float* q_input  = (const float*)d_in[0];
    const float* kv_input = (const float*)d_in[1];
    const int*   mask     = (const int*)d_in[2];    // bool -> int32 in harness
    const float* Wq = (const float*)d_in[3];
    const float* Wk = (const float*)d_in[4];
    const float* Wv = (const float*)d_in[5];
    const float* Wo = (const float*)d_in[6];
    const float* ln_gamma = (const float*)d_in[7];
    const float* ln_beta  = (const float*)d_in[8];
    const float* rope_cos = (const float*)d_in[9];
    const float* rope_sin = (const float*)d_in[10];
    float* out = (float*)d_out;

    float *pQ, *pK, *pV, *pA, *pR;
    cudaGetSymbolAddress((void**)&pQ, g_Q);
    cudaGetSymbolAddress((void**)&pK, g_K);
    cudaGetSymbolAddress((void**)&pV, g_V);
    cudaGetSymbolAddress((void**)&pA, g_A);
    cudaGetSymbolAddress((void**)&pR, g_R);

    cudaFuncSetAttribute(flash_kernel,
                         cudaFuncAttributeMaxDynamicSharedMemorySize, FL_SMEM);

    const int M = Bz * Sz;   // 8192
    dim3 ggrid(Dz / 128, M / 128);   // (16, 64)

    gemm128<<<ggrid, 256>>>(q_input,  Wq, nullptr, pQ, M, Dz, Dz);
    gemm128<<<ggrid, 256>>>(kv_input, Wk, nullptr, pK, M, Dz, Dz);
    gemm128<<<ggrid, 256>>>(kv_input, Wv, nullptr, pV, M, Dz, Dz);

    int rope_threads = Bz * Sz * NHz * 64;   // 8388608
    rope_kernel<<<rope_threads / 256, 256>>>(pQ, rope_cos, rope_sin);
    rope_kernel<<<rope_threads / 256, 256>>>(pK, rope_cos, rope_sin);

    flash_kernel<<<Bz * NHz * (Sz / 64), 256, FL_SMEM>>>(pQ, pK, pV, mask, pA);

    gemm128<<<ggrid, 256>>>(pA, Wo, q_input, pR, M, Dz, Dz);

    ln_kernel<<<M, 256>>>(pR, ln_gamma, ln_beta, out);
}

// round 9
// speedup vs baseline: 1.1217x; 1.1217x over previous
#include <cuda_runtime.h>
#include <cuda_bf16.h>
#include <cstdint>
#include <math.h>

// Problem constants
#define Bz 4
#define Sz 2048
#define Dz 2048
#define NHz 16
#define DHz 128

#define TOT (4UL*2048UL*2048UL)   // B*S*D elements

// Scratch (allocation-free rule: __device__ globals)
__device__ float g_Q[TOT];
__device__ float g_K[TOT];
__device__ float g_V[TOT];
__device__ float g_A[TOT];
__device__ float g_R[TOT];

// ===========================================================================
// tf32 helpers (base-family PTX, assembles for plain compute_103)
// ===========================================================================
__device__ __forceinline__ float tf32r(float x) {
    uint32_t u;
    asm("cvt.rna.tf32.f32 %0, %1;" : "=r"(u) : "f"(x));
    return __uint_as_float(u);
}
__device__ __forceinline__ void mma_tf32(float* c, const uint32_t* a, const uint32_t* b) {
    asm volatile(
        "mma.sync.aligned.m16n8k8.row.col.f32.tf32.tf32.f32 "
        "{%0,%1,%2,%3}, {%4,%5,%6,%7}, {%8,%9}, {%0,%1,%2,%3};"
        : "+f"(c[0]), "+f"(c[1]), "+f"(c[2]), "+f"(c[3])
        : "r"(a[0]), "r"(a[1]), "r"(a[2]), "r"(a[3]), "r"(b[0]), "r"(b[1]));
}

// ===========================================================================
// tf32 one-pass GEMM: C[M=8192, N=2048] = A @ B (+Res).
// CTA 128x128, 8 warps (2x4), warp tile 64x32, K-chunk 16, 2-stage smem
// with register prefetch. grid.z selects (Bx,Cx) vs (By,Cy) for fused K/V.
// ===========================================================================
__global__ __launch_bounds__(256, 2) void tgemm(
    const float* __restrict__ A,
    const float* __restrict__ Bx, const float* __restrict__ By,
    const float* __restrict__ Res, float* __restrict__ Cx, float* __restrict__ Cy)
{
    const float* __restrict__ B = blockIdx.z ? By : Bx;
    float* __restrict__ C = blockIdx.z ? Cy : Cx;

    __shared__ float sA[2][128][20];   // padded: frag banks 20g+tig all distinct
    __shared__ float sB[2][16][136];

    const int tid = threadIdx.x;
    const int lane = tid & 31, wid = tid >> 5;
    const int wm = wid >> 2, wn = wid & 3;
    const int g = lane >> 2, tig = lane & 3;
    const int m0 = blockIdx.y * 128, n0 = blockIdx.x * 128;

    float acc[4][4][4];
#pragma unroll
    for (int mi = 0; mi < 4; mi++)
#pragma unroll
        for (int ni = 0; ni < 4; ni++)
#pragma unroll
            for (int e = 0; e < 4; e++) acc[mi][ni][e] = 0.f;

    float ra[8], rb[8];

    auto ldg = [&](int k0) {
#pragma unroll
        for (int r = 0; r < 8; r++) {
            int e = r * 256 + tid;
            int row = e >> 4, col = e & 15;
            ra[r] = A[(long)(m0 + row) * 2048 + k0 + col];
        }
#pragma unroll
        for (int r = 0; r < 8; r++) {
            int e = r * 256 + tid;
            int row = e >> 7, col = e & 127;
            rb[r] = B[(long)(k0 + row) * 2048 + n0 + col];
        }
    };
    auto sts = [&](int st) {
#pragma unroll
        for (int r = 0; r < 8; r++) {
            int e = r * 256 + tid;
            int row = e >> 4, col = e & 15;
            sA[st][row][col] = tf32r(ra[r]);
        }
#pragma unroll
        for (int r = 0; r < 8; r++) {
            int e = r * 256 + tid;
            int row = e >> 7, col = e & 127;
            sB[st][row][col] = tf32r(rb[r]);
        }
    };

    ldg(0);
    sts(0);
    __syncthreads();

    for (int c = 0; c < 128; c++) {
        const int st = c & 1;
        if (c + 1 < 128) ldg((c + 1) * 16);   // prefetch next chunk into regs

#pragma unroll
        for (int kk = 0; kk < 16; kk += 8) {
            uint32_t af[4][4], bf[4][2];
#pragma unroll
            for (int mi = 0; mi < 4; mi++) {
                int r = wm * 64 + mi * 16 + g;
                af[mi][0] = __float_as_uint(sA[st][r][kk + tig]);
                af[mi][1] = __float_as_uint(sA[st][r + 8][kk + tig]);
                af[mi][2] = __float_as_uint(sA[st][r][kk + tig + 4]);
                af[mi][3] = __float_as_uint(sA[st][r + 8][kk + tig + 4]);
            }
#pragma unroll
            for (int ni = 0; ni < 4; ni++) {
                int cn = wn * 32 + ni * 8 + g;
                bf[ni][0] = __float_as_uint(sB[st][kk + tig][cn]);
                bf[ni][1] = __float_as_uint(sB[st][kk + tig + 4][cn]);
            }
#pragma unroll
            for (int mi = 0; mi < 4; mi++)
#pragma unroll
                for (int ni = 0; ni < 4; ni++)
                    mma_tf32(acc[mi][ni], af[mi], bf[ni]);
        }

        if (c + 1 < 128) {
            __syncthreads();
            sts((c + 1) & 1);
            __syncthreads();
        }
    }

    // Epilogue: c0,c1 = (row g, cols tig*2..+1); c2,c3 = (row g+8, same cols)
#pragma unroll
    for (int mi = 0; mi < 4; mi++) {
        int r0 = m0 + wm * 64 + mi * 16 + g;
#pragma unroll
        for (int ni = 0; ni < 4; ni++) {
            int col = n0 + wn * 32 + ni * 8 + tig * 2;
            long o0 = (long)r0 * 2048 + col;
            long o1 = (long)(r0 + 8) * 2048 + col;
            float2 v0 = { acc[mi][ni][0], acc[mi][ni][1] };
            float2 v1 = { acc[mi][ni][2], acc[mi][ni][3] };
            if (Res) {
                float2 q0 = *(const float2*)&Res[o0];
                float2 q1 = *(const float2*)&Res[o1];
                v0.x += q0.x; v0.y += q0.y;
                v1.x += q1.x; v1.y += q1.y;
            }
            *(float2*)&C[o0] = v0;
            *(float2*)&C[o1] = v1;
        }
    }
}

// ---------------------------------------------------------------------------
// RoPE on Q and K in ONE launch (keeps flash at ncu-profiled launch index 3)
// ---------------------------------------------------------------------------
__global__ void rope2_kernel(float* __restrict__ Xq, float* __restrict__ Xk,
                             const float* __restrict__ cosb,
                             const float* __restrict__ sinb)
{
    long idx = (long)blockIdx.x * blockDim.x + threadIdx.x;  // 2 * 2^23
    float* X = (idx >> 23) ? Xk : Xq;
    int t = (int)(idx & ((1 << 23) - 1));
    int i = t & 63;
    int h = (t >> 6) & 15;
    int s = (t >> 10) & 2047;
    int b = t >> 21;
    long base = ((long)(b * Sz + s)) * Dz + h * DHz + 2 * i;
    float c = cosb[s * 64 + i], sn = sinb[s * 64 + i];
    float x1 = X[base], x2 = X[base + 1];
    X[base]     = x1 * c - x2 * sn;
    X[base + 1] = x1 * sn + x2 * c;
}

// ---------------------------------------------------------------------------
// Flash attention (fp32 SIMT, exact R5 version). mask int32: nonzero==masked.
// ---------------------------------------------------------------------------
#define FL_SMEM ((64*128 + 64*129 + 64*128 + 64*64) * 4)

__global__ __launch_bounds__(256) void flash_kernel(
    const float* __restrict__ Q, const float* __restrict__ K,
    const float* __restrict__ V, const int* __restrict__ mask,
    float* __restrict__ O)
{
    extern __shared__ float sm[];
    float* sQ = sm;                 // 64 x 128
    float* sK = sQ + 64 * 128;      // 64 x 129
    float* sV = sK + 64 * 129;      // 64 x 128
    float* sS = sV + 64 * 128;      // 64 x 64

    const int tid = threadIdx.x;
    const int tx = tid & 15, ty = tid >> 4;
    const int blk = blockIdx.x;
    const int qt = blk & 31;
    const int h  = (blk >> 5) & 15;
    const int b  = blk >> 9;
    const int q0 = qt * 64;
    const float scale = 0.08838834764831845f;   // 1/sqrt(128)

#pragma unroll
    for (int r = 0; r < 32; r++) {
        int e = r * 256 + tid;
        int row = e >> 7, col = e & 127;
        sQ[row * 128 + col] = Q[((long)(b * Sz + q0 + row)) * Dz + h * DHz + col];
    }

    float m_i[4], l_i[4], o[4][8];
#pragma unroll
    for (int i = 0; i < 4; i++) {
        m_i[i] = -1e30f; l_i[i] = 0.f;
#pragma unroll
        for (int c = 0; c < 8; c++) o[i][c] = 0.f;
    }

    const int* mrow = mask + (long)b * Sz;

    for (int k0 = 0; k0 < Sz; k0 += 64) {
        __syncthreads();
#pragma unroll
        for (int r = 0; r < 32; r++) {
            int e = r * 256 + tid;
            int row = e >> 7, col = e & 127;
            long gg = ((long)(b * Sz + k0 + row)) * Dz + h * DHz + col;
            sK[row * 129 + col] = K[gg];
            sV[row * 128 + col] = V[gg];
        }
        __syncthreads();

        float accs[4][4];
#pragma unroll
        for (int i = 0; i < 4; i++)
#pragma unroll
            for (int j = 0; j < 4; j++) accs[i][j] = 0.f;

#pragma unroll 4
        for (int k = 0; k < 128; k++) {
            float a[4], bb[4];
#pragma unroll
            for (int i = 0; i < 4; i++) a[i]  = sQ[(ty * 4 + i) * 128 + k];
#pragma unroll
            for (int j = 0; j < 4; j++) bb[j] = sK[(tx * 4 + j) * 129 + k];
#pragma unroll
            for (int i = 0; i < 4; i++)
#pragma unroll
                for (int j = 0; j < 4; j++) accs[i][j] += a[i] * bb[j];
        }

        float sv[4][4];
#pragma unroll
        for (int j = 0; j < 4; j++) {
            bool msk = mrow[k0 + tx * 4 + j] != 0;
#pragma unroll
            for (int i = 0; i < 4; i++)
                sv[i][j] = msk ? -1e30f : accs[i][j] * scale;
        }

#pragma unroll
        for (int i = 0; i < 4; i++) {
            float tm = fmaxf(fmaxf(sv[i][0], sv[i][1]), fmaxf(sv[i][2], sv[i][3]));
#pragma unroll
            for (int d = 1; d < 16; d <<= 1)
                tm = fmaxf(tm, __shfl_xor_sync(0xffffffffu, tm, d));
            float nm = fmaxf(m_i[i], tm);
            float corr = __expf(m_i[i] - nm);
            float p[4], ps = 0.f;
#pragma unroll
            for (int j = 0; j < 4; j++) { p[j] = __expf(sv[i][j] - nm); ps += p[j]; }
#pragma unroll
            for (int d = 1; d < 16; d <<= 1)
                ps += __shfl_xor_sync(0xffffffffu, ps, d);
            l_i[i] = l_i[i] * corr + ps;
            m_i[i] = nm;
#pragma unroll
            for (int c = 0; c < 8; c++) o[i][c] *= corr;
#pragma unroll
            for (int j = 0; j < 4; j++)
                sS[(ty * 4 + i) * 64 + tx * 4 + j] = p[j];
        }
        __syncthreads();

#pragma unroll 4
        for (int kc = 0; kc < 64; kc++) {
            float4 v0 = *(const float4*)&sV[kc * 128 + tx * 8];
            float4 v1 = *(const float4*)&sV[kc * 128 + tx * 8 + 4];
#pragma unroll
            for (int i = 0; i < 4; i++) {
                float s = sS[(ty * 4 + i) * 64 + kc];
                o[i][0] += s * v0.x; o[i][1] += s * v0.y;
                o[i][2] += s * v0.z; o[i][3] += s * v0.w;
                o[i][4] += s * v1.x; o[i][5] += s * v1.y;
                o[i][6] += s * v1.z; o[i][7] += s * v1.w;
            }
        }
    }

#pragma unroll
    for (int i = 0; i < 4; i++) {
        float inv = 1.f / l_i[i];
        long base = ((long)(b * Sz + q0 + ty * 4 + i)) * Dz + h * DHz + tx * 8;
        float4 r0 = { o[i][0]*inv, o[i][1]*inv, o[i][2]*inv, o[i][3]*inv };
        float4 r1 = { o[i][4]*inv, o[i][5]*inv, o[i][6]*inv, o[i][7]*inv };
        *(float4*)&O[base]     = r0;
        *(float4*)&O[base + 4] = r1;
    }
}

// ---------------------------------------------------------------------------
// LayerNorm over last dim (2048), one CTA per row
// ---------------------------------------------------------------------------
__global__ __launch_bounds__(256) void ln_kernel(
    const float* __restrict__ X, const float* __restrict__ gamma,
    const float* __restrict__ beta, float* __restrict__ Y)
{
    const int row = blockIdx.x;
    const int tid = threadIdx.x;
    const float* x = X + (long)row * Dz;

    float v[8], s = 0.f, s2 = 0.f;
#pragma unroll
    for (int r = 0; r < 8; r++) {
        float t = x[r * 256 + tid];
        v[r] = t; s += t; s2 += t * t;
    }
#pragma unroll
    for (int d = 16; d >= 1; d >>= 1) {
        s  += __shfl_xor_sync(0xffffffffu, s,  d);
        s2 += __shfl_xor_sync(0xffffffffu, s2, d);
    }
    __shared__ float rs[8], rs2[8];
    __shared__ float s_mean, s_rstd;
    int wid = tid >> 5, lane = tid & 31;
    if (lane == 0) { rs[wid] = s; rs2[wid] = s2; }
    __syncthreads();
    if (tid == 0) {
        float S = 0.f, S2 = 0.f;
        for (int w = 0; w < 8; w++) { S += rs[w]; S2 += rs2[w]; }
        float mu = S * (1.f / 2048.f);
        float var = S2 * (1.f / 2048.f) - mu * mu;
        s_mean = mu;
        s_rstd = rsqrtf(var + 1e-5f);
    }
    __syncthreads();
    float mu = s_mean, rstd = s_rstd;
    float* y = Y + (long)row * Dz;
#pragma unroll
    for (int r = 0; r < 8; r++) {
        int c = r * 256 + tid;
        y[c] = (v[r] - mu) * rstd * gamma[c] + beta[c];
    }
}

// ---------------------------------------------------------------------------
extern "C" void kernel_launch(void* const* d_in, const int* in_sizes, int n_in,
                              void* d_out, int out_size)
{
    const float* q_input  = (const float*)d_in[0];
    const float* kv_input = (const float*)d_in[1];
    const int*   mask     = (const int*)d_in[2];    // bool -> int32 in harness
    const float* Wq = (const float*)d_in[3];
    const float* Wk = (const float*)d_in[4];
    const float* Wv = (const float*)d_in[5];
    const float* Wo = (const float*)d_in[6];
    const float* ln_gamma = (const float*)d_in[7];
    const float* ln_beta  = (const float*)d_in[8];
    const float* rope_cos = (const float*)d_in[9];
    const float* rope_sin = (const float*)d_in[10];
    float* out = (float*)d_out;

    float *pQ, *pK, *pV, *pA, *pR;
    cudaGetSymbolAddress((void**)&pQ, g_Q);
    cudaGetSymbolAddress((void**)&pK, g_K);
    cudaGetSymbolAddress((void**)&pV, g_V);
    cudaGetSymbolAddress((void**)&pA, g_A);
    cudaGetSymbolAddress((void**)&pR, g_R);

    cudaFuncSetAttribute(flash_kernel,
                         cudaFuncAttributeMaxDynamicSharedMemorySize, FL_SMEM);

    const int M = Bz * Sz;   // 8192

    // Launch order chosen so flash_kernel sits at ncu's profiled index 3.
    dim3 gq(16, 64, 1), gkv(16, 64, 2);

    tgemm<<<gq, 256>>>(q_input, Wq, Wq, nullptr, pQ, pQ);                 // 0
    tgemm<<<gkv, 256>>>(kv_input, Wk, Wv, nullptr, pK, pV);               // 1

    long rope_threads = 2L * Bz * Sz * NHz * 64;   // 2 * 2^23
    rope2_kernel<<<(int)(rope_threads / 256), 256>>>(pQ, pK,
                                                     rope_cos, rope_sin); // 2

    flash_kernel<<<Bz * NHz * (Sz / 64), 256, FL_SMEM>>>(pQ, pK, pV,
                                                         mask, pA);       // 3

    tgemm<<<gq, 256>>>(pA, Wo, Wo, q_input, pR, pR);                      // 4

    ln_kernel<<<M, 256>>>(pR, ln_gamma, ln_beta, out);                    // 5
}

// round 12
// speedup vs baseline: 2.6947x; 2.4024x over previous
#include <cuda_runtime.h>
#include <cuda_bf16.h>
#include <cstdint>
#include <math.h>

// Problem constants
#define Bz 4
#define Sz 2048
#define Dz 2048
#define NHz 16
#define DHz 128

#define TOT (4UL*2048UL*2048UL)   // B*S*D elements

// Scratch (allocation-free rule: __device__ globals)
__device__ float g_Q[TOT];
__device__ float g_K[TOT];
__device__ float g_V[TOT];
__device__ float g_A[TOT];
__device__ float g_R[TOT];
__device__ float g_KVc[TOT];      // compacted kv_input
__device__ int   g_cidx[Bz * Sz];
__device__ int   g_cnt[Bz];

// ===========================================================================
// tf32 helpers (base-family PTX, assembles for plain compute_103)
// ===========================================================================
__device__ __forceinline__ float tf32r(float x) {
    uint32_t u;
    asm("cvt.rna.tf32.f32 %0, %1;" : "=r"(u) : "f"(x));
    return __uint_as_float(u);
}
__device__ __forceinline__ void mma_tf32(float* c, const uint32_t* a, const uint32_t* b) {
    asm volatile(
        "mma.sync.aligned.m16n8k8.row.col.f32.tf32.tf32.f32 "
        "{%0,%1,%2,%3}, {%4,%5,%6,%7}, {%8,%9}, {%0,%1,%2,%3};"
        : "+f"(c[0]), "+f"(c[1]), "+f"(c[2]), "+f"(c[3])
        : "r"(a[0]), "r"(a[1]), "r"(a[2]), "r"(a[3]), "r"(b[0]), "r"(b[1]));
}

// ===========================================================================
// Mask compaction: per batch, list of unmasked key positions + count.
// One 1024-thread CTA per batch; Hillis-Steele inclusive scan over pair sums.
// ===========================================================================
__global__ __launch_bounds__(1024) void compact_kernel(
    const int* __restrict__ mask, int* __restrict__ cidx, int* __restrict__ cnt)
{
    __shared__ int ssum[1024];
    const int b = blockIdx.x, t = threadIdx.x;
    const int* m = mask + b * Sz;
    int u0 = (m[2 * t] == 0) ? 1 : 0;
    int u1 = (m[2 * t + 1] == 0) ? 1 : 0;
    int pair = u0 + u1;
    ssum[t] = pair;
    __syncthreads();
#pragma unroll
    for (int d = 1; d < 1024; d <<= 1) {
        int v = (t >= d) ? ssum[t - d] : 0;
        __syncthreads();
        ssum[t] += v;
        __syncthreads();
    }
    int excl = ssum[t] - pair;
    if (u0) cidx[b * Sz + excl] = 2 * t;
    if (u1) cidx[b * Sz + excl + u0] = 2 * t + 1;
    if (t == 1023) cnt[b] = ssum[1023];
}

// Gather compacted kv rows (rows >= cnt zero-filled)
__global__ __launch_bounds__(256) void gather_kernel(
    const float* __restrict__ kv, const int* __restrict__ cidx,
    const int* __restrict__ cnt, float* __restrict__ out)
{
    const int row = blockIdx.x;              // 0..8191
    const int b = row >> 11, r = row & 2047;
    const int n = cnt[b];
    float4* dst = (float4*)(out + (long)row * Dz);
    if (r < n) {
        const float4* src = (const float4*)(kv + ((long)(b * Sz + cidx[b * Sz + r])) * Dz);
#pragma unroll 2
        for (int i = threadIdx.x; i < 512; i += 256) dst[i] = src[i];
    } else {
        float4 z = {0.f, 0.f, 0.f, 0.f};
#pragma unroll 2
        for (int i = threadIdx.x; i < 512; i += 256) dst[i] = z;
    }
}

// ===========================================================================
// tf32 one-pass GEMM: C[M=8192, N=2048] = A @ B (+Res).
// CTA 128x128, 8 warps (2x4), warp tile 64x32, K-chunk 16, 2-stage smem
// with register prefetch. grid.z selects (Bx,Cx) vs (By,Cy) for fused K/V.
// If cnt != nullptr: early-exit CTAs whose m-tile is entirely >= cnt[batch].
// ===========================================================================
__global__ __launch_bounds__(256, 2) void tgemm(
    const float* __restrict__ A,
    const float* __restrict__ Bx, const float* __restrict__ By,
    const float* __restrict__ Res, float* __restrict__ Cx, float* __restrict__ Cy,
    const int* __restrict__ cnt)
{
    const float* __restrict__ B = blockIdx.z ? By : Bx;
    float* __restrict__ C = blockIdx.z ? Cy : Cx;

    const int m0 = blockIdx.y * 128, n0 = blockIdx.x * 128;
    if (cnt) {
        int b = m0 >> 11, local = m0 & 2047;
        if (local >= cnt[b]) return;       // whole tile beyond compact count
    }

    __shared__ float sA[2][128][20];
    __shared__ float sB[2][16][136];

    const int tid = threadIdx.x;
    const int lane = tid & 31, wid = tid >> 5;
    const int wm = wid >> 2, wn = wid & 3;
    const int g = lane >> 2, tig = lane & 3;

    float acc[4][4][4];
#pragma unroll
    for (int mi = 0; mi < 4; mi++)
#pragma unroll
        for (int ni = 0; ni < 4; ni++)
#pragma unroll
            for (int e = 0; e < 4; e++) acc[mi][ni][e] = 0.f;

    float ra[8], rb[8];

    auto ldg = [&](int k0) {
#pragma unroll
        for (int r = 0; r < 8; r++) {
            int e = r * 256 + tid;
            int row = e >> 4, col = e & 15;
            ra[r] = A[(long)(m0 + row) * 2048 + k0 + col];
        }
#pragma unroll
        for (int r = 0; r < 8; r++) {
            int e = r * 256 + tid;
            int row = e >> 7, col = e & 127;
            rb[r] = B[(long)(k0 + row) * 2048 + n0 + col];
        }
    };
    auto sts = [&](int st) {
#pragma unroll
        for (int r = 0; r < 8; r++) {
            int e = r * 256 + tid;
            int row = e >> 4, col = e & 15;
            sA[st][row][col] = tf32r(ra[r]);
        }
#pragma unroll
        for (int r = 0; r < 8; r++) {
            int e = r * 256 + tid;
            int row = e >> 7, col = e & 127;
            sB[st][row][col] = tf32r(rb[r]);
        }
    };

    ldg(0);
    sts(0);
    __syncthreads();

    for (int c = 0; c < 128; c++) {
        const int st = c & 1;
        if (c + 1 < 128) ldg((c + 1) * 16);

#pragma unroll
        for (int kk = 0; kk < 16; kk += 8) {
            uint32_t af[4][4], bf[4][2];
#pragma unroll
            for (int mi = 0; mi < 4; mi++) {
                int r = wm * 64 + mi * 16 + g;
                af[mi][0] = __float_as_uint(sA[st][r][kk + tig]);
                af[mi][1] = __float_as_uint(sA[st][r + 8][kk + tig]);
                af[mi][2] = __float_as_uint(sA[st][r][kk + tig + 4]);
                af[mi][3] = __float_as_uint(sA[st][r + 8][kk + tig + 4]);
            }
#pragma unroll
            for (int ni = 0; ni < 4; ni++) {
                int cn = wn * 32 + ni * 8 + g;
                bf[ni][0] = __float_as_uint(sB[st][kk + tig][cn]);
                bf[ni][1] = __float_as_uint(sB[st][kk + tig + 4][cn]);
            }
#pragma unroll
            for (int mi = 0; mi < 4; mi++)
#pragma unroll
                for (int ni = 0; ni < 4; ni++)
                    mma_tf32(acc[mi][ni], af[mi], bf[ni]);
        }

        if (c + 1 < 128) {
            __syncthreads();
            sts((c + 1) & 1);
            __syncthreads();
        }
    }

#pragma unroll
    for (int mi = 0; mi < 4; mi++) {
        int r0 = m0 + wm * 64 + mi * 16 + g;
#pragma unroll
        for (int ni = 0; ni < 4; ni++) {
            int col = n0 + wn * 32 + ni * 8 + tig * 2;
            long o0 = (long)r0 * 2048 + col;
            long o1 = (long)(r0 + 8) * 2048 + col;
            float2 v0 = { acc[mi][ni][0], acc[mi][ni][1] };
            float2 v1 = { acc[mi][ni][2], acc[mi][ni][3] };
            if (Res) {
                float2 q0 = *(const float2*)&Res[o0];
                float2 q1 = *(const float2*)&Res[o1];
                v0.x += q0.x; v0.y += q0.y;
                v1.x += q1.x; v1.y += q1.y;
            }
            *(float2*)&C[o0] = v0;
            *(float2*)&C[o1] = v1;
        }
    }
}

// ---------------------------------------------------------------------------
// RoPE on Q (original order) and compacted K (angle from original position)
// ---------------------------------------------------------------------------
__global__ void rope2_kernel(float* __restrict__ Xq, float* __restrict__ Xk,
                             const float* __restrict__ cosb,
                             const float* __restrict__ sinb,
                             const int* __restrict__ cidx,
                             const int* __restrict__ cnt)
{
    long idx = (long)blockIdx.x * blockDim.x + threadIdx.x;  // 2 * 2^23
    int isK = (int)(idx >> 23);
    int t = (int)(idx & ((1 << 23) - 1));
    int i = t & 63;
    int h = (t >> 6) & 15;
    int s = (t >> 10) & 2047;
    int b = t >> 21;
    int s_ang = s;
    float* X = Xq;
    if (isK) {
        if (s >= cnt[b]) return;          // beyond compact count
        s_ang = cidx[b * Sz + s];         // original position for angle
        X = Xk;
    }
    long base = ((long)(b * Sz + s)) * Dz + h * DHz + 2 * i;
    float c = cosb[s_ang * 64 + i], sn = sinb[s_ang * 64 + i];
    float x1 = X[base], x2 = X[base + 1];
    X[base]     = x1 * c - x2 * sn;
    X[base + 1] = x1 * sn + x2 * c;
}

// ---------------------------------------------------------------------------
// Flash attention over COMPACTED keys: loop ceil(cnt/64) tiles,
// mask only by compact index >= cnt (numerically identical to -inf mask).
// ---------------------------------------------------------------------------
#define FL_SMEM ((64*128 + 64*129 + 64*128 + 64*64) * 4)

__global__ __launch_bounds__(256) void flash_kernel(
    const float* __restrict__ Q, const float* __restrict__ K,
    const float* __restrict__ V, const int* __restrict__ cnt,
    float* __restrict__ O)
{
    extern __shared__ float sm[];
    float* sQ = sm;                 // 64 x 128
    float* sK = sQ + 64 * 128;      // 64 x 129
    float* sV = sK + 64 * 129;      // 64 x 128
    float* sS = sV + 64 * 128;      // 64 x 64

    const int tid = threadIdx.x;
    const int tx = tid & 15, ty = tid >> 4;
    const int blk = blockIdx.x;
    const int qt = blk & 31;
    const int h  = (blk >> 5) & 15;
    const int b  = blk >> 9;
    const int q0 = qt * 64;
    const float scale = 0.08838834764831845f;   // 1/sqrt(128)
    const int kmax = cnt[b];

#pragma unroll
    for (int r = 0; r < 32; r++) {
        int e = r * 256 + tid;
        int row = e >> 7, col = e & 127;
        sQ[row * 128 + col] = Q[((long)(b * Sz + q0 + row)) * Dz + h * DHz + col];
    }

    float m_i[4], l_i[4], o[4][8];
#pragma unroll
    for (int i = 0; i < 4; i++) {
        m_i[i] = -1e30f; l_i[i] = 0.f;
#pragma unroll
        for (int c = 0; c < 8; c++) o[i][c] = 0.f;
    }

    for (int k0 = 0; k0 < kmax; k0 += 64) {
        __syncthreads();
#pragma unroll
        for (int r = 0; r < 32; r++) {
            int e = r * 256 + tid;
            int row = e >> 7, col = e & 127;
            long gg = ((long)(b * Sz + k0 + row)) * Dz + h * DHz + col;
            sK[row * 129 + col] = K[gg];
            sV[row * 128 + col] = V[gg];
        }
        __syncthreads();

        float accs[4][4];
#pragma unroll
        for (int i = 0; i < 4; i++)
#pragma unroll
            for (int j = 0; j < 4; j++) accs[i][j] = 0.f;

#pragma unroll 4
        for (int k = 0; k < 128; k++) {
            float a[4], bb[4];
#pragma unroll
            for (int i = 0; i < 4; i++) a[i]  = sQ[(ty * 4 + i) * 128 + k];
#pragma unroll
            for (int j = 0; j < 4; j++) bb[j] = sK[(tx * 4 + j) * 129 + k];
#pragma unroll
            for (int i = 0; i < 4; i++)
#pragma unroll
                for (int j = 0; j < 4; j++) accs[i][j] += a[i] * bb[j];
        }

        float sv[4][4];
#pragma unroll
        for (int j = 0; j < 4; j++) {
            bool msk = (k0 + tx * 4 + j) >= kmax;   // only tail padding masked
#pragma unroll
            for (int i = 0; i < 4; i++)
                sv[i][j] = msk ? -1e30f : accs[i][j] * scale;
        }

#pragma unroll
        for (int i = 0; i < 4; i++) {
            float tm = fmaxf(fmaxf(sv[i][0], sv[i][1]), fmaxf(sv[i][2], sv[i][3]));
#pragma unroll
            for (int d = 1; d < 16; d <<= 1)
                tm = fmaxf(tm, __shfl_xor_sync(0xffffffffu, tm, d));
            float nm = fmaxf(m_i[i], tm);
            float corr = __expf(m_i[i] - nm);
            float p[4], ps = 0.f;
#pragma unroll
            for (int j = 0; j < 4; j++) { p[j] = __expf(sv[i][j] - nm); ps += p[j]; }
#pragma unroll
            for (int d = 1; d < 16; d <<= 1)
                ps += __shfl_xor_sync(0xffffffffu, ps, d);
            l_i[i] = l_i[i] * corr + ps;
            m_i[i] = nm;
#pragma unroll
            for (int c = 0; c < 8; c++) o[i][c] *= corr;
#pragma unroll
            for (int j = 0; j < 4; j++)
                sS[(ty * 4 + i) * 64 + tx * 4 + j] = p[j];
        }
        __syncthreads();

#pragma unroll 4
        for (int kc = 0; kc < 64; kc++) {
            float4 v0 = *(const float4*)&sV[kc * 128 + tx * 8];
            float4 v1 = *(const float4*)&sV[kc * 128 + tx * 8 + 4];
#pragma unroll
            for (int i = 0; i < 4; i++) {
                float s = sS[(ty * 4 + i) * 64 + kc];
                o[i][0] += s * v0.x; o[i][1] += s * v0.y;
                o[i][2] += s * v0.z; o[i][3] += s * v0.w;
                o[i][4] += s * v1.x; o[i][5] += s * v1.y;
                o[i][6] += s * v1.z; o[i][7] += s * v1.w;
            }
        }
    }

#pragma unroll
    for (int i = 0; i < 4; i++) {
        float inv = 1.f / l_i[i];
        long base = ((long)(b * Sz + q0 + ty * 4 + i)) * Dz + h * DHz + tx * 8;
        float4 r0 = { o[i][0]*inv, o[i][1]*inv, o[i][2]*inv, o[i][3]*inv };
        float4 r1 = { o[i][4]*inv, o[i][5]*inv, o[i][6]*inv, o[i][7]*inv };
        *(float4*)&O[base]     = r0;
        *(float4*)&O[base + 4] = r1;
    }
}

// ---------------------------------------------------------------------------
// LayerNorm over last dim (2048), one CTA per row
// ---------------------------------------------------------------------------
__global__ __launch_bounds__(256) void ln_kernel(
    const float* __restrict__ X, const float* __restrict__ gamma,
    const float* __restrict__ beta, float* __restrict__ Y)
{
    const int row = blockIdx.x;
    const int tid = threadIdx.x;
    const float* x = X + (long)row * Dz;

    float v[8], s = 0.f, s2 = 0.f;
#pragma unroll
    for (int r = 0; r < 8; r++) {
        float t = x[r * 256 + tid];
        v[r] = t; s += t; s2 += t * t;
    }
#pragma unroll
    for (int d = 16; d >= 1; d >>= 1) {
        s  += __shfl_xor_sync(0xffffffffu, s,  d);
        s2 += __shfl_xor_sync(0xffffffffu, s2, d);
    }
    __shared__ float rs[8], rs2[8];
    __shared__ float s_mean, s_rstd;
    int wid = tid >> 5, lane = tid & 31;
    if (lane == 0) { rs[wid] = s; rs2[wid] = s2; }
    __syncthreads();
    if (tid == 0) {
        float S = 0.f, S2 = 0.f;
        for (int w = 0; w < 8; w++) { S += rs[w]; S2 += rs2[w]; }
        float mu = S * (1.f / 2048.f);
        float var = S2 * (1.f / 2048.f) - mu * mu;
        s_mean = mu;
        s_rstd = rsqrtf(var + 1e-5f);
    }
    __syncthreads();
    float mu = s_mean, rstd = s_rstd;
    float* y = Y + (long)row * Dz;
#pragma unroll
    for (int r = 0; r < 8; r++) {
        int c = r * 256 + tid;
        y[c] = (v[r] - mu) * rstd * gamma[c] + beta[c];
    }
}

// ---------------------------------------------------------------------------
extern "C" void kernel_launch(void* const* d_in, const int* in_sizes, int n_in,
                              void* d_out, int out_size)
{
    const float* q_input  = (const float*)d_in[0];
    const float* kv_input = (const float*)d_in[1];
    const int*   mask     = (const int*)d_in[2];    // bool -> int32 in harness
    const float* Wq = (const float*)d_in[3];
    const float* Wk = (const float*)d_in[4];
    const float* Wv = (const float*)d_in[5];
    const float* Wo = (const float*)d_in[6];
    const float* ln_gamma = (const float*)d_in[7];
    const float* ln_beta  = (const float*)d_in[8];
    const float* rope_cos = (const float*)d_in[9];
    const float* rope_sin = (const float*)d_in[10];
    float* out = (float*)d_out;

    float *pQ, *pK, *pV, *pA, *pR, *pKVc;
    int *pcidx, *pcnt;
    cudaGetSymbolAddress((void**)&pQ, g_Q);
    cudaGetSymbolAddress((void**)&pK, g_K);
    cudaGetSymbolAddress((void**)&pV, g_V);
    cudaGetSymbolAddress((void**)&pA, g_A);
    cudaGetSymbolAddress((void**)&pR, g_R);
    cudaGetSymbolAddress((void**)&pKVc, g_KVc);
    cudaGetSymbolAddress((void**)&pcidx, g_cidx);
    cudaGetSymbolAddress((void**)&pcnt, g_cnt);

    cudaFuncSetAttribute(flash_kernel,
                         cudaFuncAttributeMaxDynamicSharedMemorySize, FL_SMEM);

    const int M = Bz * Sz;   // 8192
    dim3 gq(16, 64, 1), gkv(16, 64, 2);

    // mask compaction + gather
    compact_kernel<<<Bz, 1024>>>(mask, pcidx, pcnt);
    gather_kernel<<<M, 256>>>(kv_input, pcidx, pcnt, pKVc);

    // projections (K/V on compacted rows, with early-exit)
    tgemm<<<gq, 256>>>(q_input, Wq, Wq, nullptr, pQ, pQ, nullptr);
    tgemm<<<gkv, 256>>>(pKVc, Wk, Wv, nullptr, pK, pV, pcnt);

    // RoPE (Q full; K compacted, angles from original positions)
    long rope_threads = 2L * Bz * Sz * NHz * 64;
    rope2_kernel<<<(int)(rope_threads / 256), 256>>>(pQ, pK, rope_cos, rope_sin,
                                                     pcidx, pcnt);

    // attention over compacted keys
    flash_kernel<<<Bz * NHz * (Sz / 64), 256, FL_SMEM>>>(pQ, pK, pV, pcnt, pA);

    // output projection + residual
    tgemm<<<gq, 256>>>(pA, Wo, Wo, q_input, pR, pR, nullptr);

    // LayerNorm
    ln_kernel<<<M, 256>>>(pR, ln_gamma, ln_beta, out);
}

// round 13
// speedup vs baseline: 2.8470x; 1.0565x over previous
#include <cuda_runtime.h>
#include <cuda_bf16.h>
#include <cstdint>
#include <math.h>

// Problem constants
#define Bz 4
#define Sz 2048
#define Dz 2048
#define NHz 16
#define DHz 128

#define TOT (4UL*2048UL*2048UL)   // B*S*D elements

// Scratch (allocation-free rule: __device__ globals)
__device__ float g_Q[TOT];
__device__ float g_K[TOT];
__device__ float g_V[TOT];
__device__ float g_A[TOT];
__device__ float g_R[TOT];
__device__ float g_KVc[TOT];      // compacted kv_input
__device__ int   g_cidx[Bz * Sz];
__device__ int   g_cnt[Bz];

// ===========================================================================
// tf32 helpers (base-family PTX, assembles for plain compute_103)
// ===========================================================================
__device__ __forceinline__ float tf32r(float x) {
    uint32_t u;
    asm("cvt.rna.tf32.f32 %0, %1;" : "=r"(u) : "f"(x));
    return __uint_as_float(u);
}
__device__ __forceinline__ void mma_tf32(float* c, const uint32_t* a, const uint32_t* b) {
    asm volatile(
        "mma.sync.aligned.m16n8k8.row.col.f32.tf32.tf32.f32 "
        "{%0,%1,%2,%3}, {%4,%5,%6,%7}, {%8,%9}, {%0,%1,%2,%3};"
        : "+f"(c[0]), "+f"(c[1]), "+f"(c[2]), "+f"(c[3])
        : "r"(a[0]), "r"(a[1]), "r"(a[2]), "r"(a[3]), "r"(b[0]), "r"(b[1]));
}

// ===========================================================================
// Mask compaction: per batch, list of unmasked key positions + count.
// ===========================================================================
__global__ __launch_bounds__(1024) void compact_kernel(
    const int* __restrict__ mask, int* __restrict__ cidx, int* __restrict__ cnt)
{
    __shared__ int ssum[1024];
    const int b = blockIdx.x, t = threadIdx.x;
    const int* m = mask + b * Sz;
    int u0 = (m[2 * t] == 0) ? 1 : 0;
    int u1 = (m[2 * t + 1] == 0) ? 1 : 0;
    int pair = u0 + u1;
    ssum[t] = pair;
    __syncthreads();
#pragma unroll
    for (int d = 1; d < 1024; d <<= 1) {
        int v = (t >= d) ? ssum[t - d] : 0;
        __syncthreads();
        ssum[t] += v;
        __syncthreads();
    }
    int excl = ssum[t] - pair;
    if (u0) cidx[b * Sz + excl] = 2 * t;
    if (u1) cidx[b * Sz + excl + u0] = 2 * t + 1;
    if (t == 1023) cnt[b] = ssum[1023];
}

// Gather compacted kv rows (rows >= cnt zero-filled)
__global__ __launch_bounds__(256) void gather_kernel(
    const float* __restrict__ kv, const int* __restrict__ cidx,
    const int* __restrict__ cnt, float* __restrict__ out)
{
    const int row = blockIdx.x;              // 0..8191
    const int b = row >> 11, r = row & 2047;
    const int n = cnt[b];
    float4* dst = (float4*)(out + (long)row * Dz);
    if (r < n) {
        const float4* src = (const float4*)(kv + ((long)(b * Sz + cidx[b * Sz + r])) * Dz);
#pragma unroll 2
        for (int i = threadIdx.x; i < 512; i += 256) dst[i] = src[i];
    } else {
        float4 z = {0.f, 0.f, 0.f, 0.f};
#pragma unroll 2
        for (int i = threadIdx.x; i < 512; i += 256) dst[i] = z;
    }
}

// ===========================================================================
// tf32 GEMM with FRAGMENT-MAJOR smem:
//   A stage: [kblock(2)][subtile(8)][lane(32)][reg(4)]  -> 1x LDS.128 / frag
//   B stage: [kblock(2)][ntile(16)*66f stride][lane(32)][reg(2)] -> 1x LDS.64
// Producer stores each ldg'ed element at its mma-fragment address (tf32-rounded).
// Index map (m16n8k8, lane l: g=l>>2, tig=l&3):
//   A elem (row,col): subtile=row/16, rr=row%16, kb=col/8, c=col%8
//     lane'=(rr&7)*4+(c&3), reg=(rr>>3)+2*(c>>2)
//   B elem (k,n): kb=k/8, kk=k%8, ntile=n/8, nn=n%8
//     lane'=nn*4+(kk&3), reg=kk>>2
// ===========================================================================
#define A_KB_STRIDE 1024               // floats: 8 subtiles * 128
#define A_STAGE     2048               // floats
#define B_NT_STRIDE 66                 // floats: 64 + 2 pad (kills 8-way STS conflict)
#define B_KB_STRIDE (16 * B_NT_STRIDE) // 1056
#define B_STAGE     (2 * B_KB_STRIDE)  // 2112

__global__ __launch_bounds__(256, 2) void tgemm(
    const float* __restrict__ A,
    const float* __restrict__ Bx, const float* __restrict__ By,
    const float* __restrict__ Res, float* __restrict__ Cx, float* __restrict__ Cy,
    const int* __restrict__ cnt)
{
    const float* __restrict__ B = blockIdx.z ? By : Bx;
    float* __restrict__ C = blockIdx.z ? Cy : Cx;

    const int m0 = blockIdx.y * 128, n0 = blockIdx.x * 128;
    if (cnt) {
        int b = m0 >> 11, local = m0 & 2047;
        if (local >= cnt[b]) return;
    }

    __shared__ float sAf[2][A_STAGE];
    __shared__ float sBf[2][B_STAGE];

    const int tid = threadIdx.x;
    const int lane = tid & 31, wid = tid >> 5;
    const int wm = wid >> 2, wn = wid & 3;
    const int g = lane >> 2, tig = lane & 3;
    (void)g; (void)tig;

    // --- producer constant addressing ---
    // A: rr = tid>>4 (0..15), col = tid&15 -> constant across r; addr = constA + r*128
    const int rrA = tid >> 4, colA = tid & 15;
    const int kbA = colA >> 3, cA = colA & 7;
    const int constA = kbA * A_KB_STRIDE
                     + ((rrA & 7) * 4 + (cA & 3)) * 4
                     + (rrA >> 3) + 2 * (cA >> 2);
    // B: n = tid&127 constant; k = r*2 + (tid>>7)
    const int nB = tid & 127, hiB = tid >> 7;
    const int ntB = nB >> 3, nnB = nB & 7;

    float acc[4][4][4];
#pragma unroll
    for (int mi = 0; mi < 4; mi++)
#pragma unroll
        for (int ni = 0; ni < 4; ni++)
#pragma unroll
            for (int e = 0; e < 4; e++) acc[mi][ni][e] = 0.f;

    float ra[8], rb[8];

    auto ldg = [&](int k0) {
#pragma unroll
        for (int r = 0; r < 8; r++)
            ra[r] = A[(long)(m0 + r * 16 + rrA) * 2048 + k0 + colA];
#pragma unroll
        for (int r = 0; r < 8; r++)
            rb[r] = B[(long)(k0 + r * 2 + hiB) * 2048 + n0 + nB];
    };
    auto sts = [&](int st) {
#pragma unroll
        for (int r = 0; r < 8; r++)
            sAf[st][constA + r * 128] = tf32r(ra[r]);
#pragma unroll
        for (int r = 0; r < 8; r++) {
            int k = r * 2 + hiB;
            int kb = k >> 3, kk = k & 7;
            int addr = kb * B_KB_STRIDE + ntB * B_NT_STRIDE
                     + (nnB * 4 + (kk & 3)) * 2 + (kk >> 2);
            sBf[st][addr] = tf32r(rb[r]);
        }
    };

    ldg(0);
    sts(0);
    __syncthreads();

    for (int c = 0; c < 128; c++) {
        const int st = c & 1;
        if (c + 1 < 128) ldg((c + 1) * 16);

#pragma unroll
        for (int kb = 0; kb < 2; kb++) {
            uint4 af[4];
            uint2 bf[4];
#pragma unroll
            for (int mi = 0; mi < 4; mi++)
                af[mi] = *(const uint4*)&sAf[st][kb * A_KB_STRIDE
                                                + (wm * 4 + mi) * 128 + lane * 4];
#pragma unroll
            for (int ni = 0; ni < 4; ni++)
                bf[ni] = *(const uint2*)&sBf[st][kb * B_KB_STRIDE
                                                + (wn * 4 + ni) * B_NT_STRIDE + lane * 2];
#pragma unroll
            for (int mi = 0; mi < 4; mi++)
#pragma unroll
                for (int ni = 0; ni < 4; ni++)
                    mma_tf32(acc[mi][ni], (const uint32_t*)&af[mi],
                             (const uint32_t*)&bf[ni]);
        }

        if (c + 1 < 128) {
            __syncthreads();
            sts((c + 1) & 1);
            __syncthreads();
        }
    }

    // Epilogue (fragment: c0,c1 = row g cols tig*2..+1; c2,c3 = row g+8)
    const int gg = lane >> 2, tt = lane & 3;
#pragma unroll
    for (int mi = 0; mi < 4; mi++) {
        int r0 = m0 + wm * 64 + mi * 16 + gg;
#pragma unroll
        for (int ni = 0; ni < 4; ni++) {
            int col = n0 + wn * 32 + ni * 8 + tt * 2;
            long o0 = (long)r0 * 2048 + col;
            long o1 = (long)(r0 + 8) * 2048 + col;
            float2 v0 = { acc[mi][ni][0], acc[mi][ni][1] };
            float2 v1 = { acc[mi][ni][2], acc[mi][ni][3] };
            if (Res) {
                float2 q0 = *(const float2*)&Res[o0];
                float2 q1 = *(const float2*)&Res[o1];
                v0.x += q0.x; v0.y += q0.y;
                v1.x += q1.x; v1.y += q1.y;
            }
            *(float2*)&C[o0] = v0;
            *(float2*)&C[o1] = v1;
        }
    }
}

// ---------------------------------------------------------------------------
// RoPE on Q (original order) and compacted K (angle from original position)
// ---------------------------------------------------------------------------
__global__ void rope2_kernel(float* __restrict__ Xq, float* __restrict__ Xk,
                             const float* __restrict__ cosb,
                             const float* __restrict__ sinb,
                             const int* __restrict__ cidx,
                             const int* __restrict__ cnt)
{
    long idx = (long)blockIdx.x * blockDim.x + threadIdx.x;  // 2 * 2^23
    int isK = (int)(idx >> 23);
    int t = (int)(idx & ((1 << 23) - 1));
    int i = t & 63;
    int h = (t >> 6) & 15;
    int s = (t >> 10) & 2047;
    int b = t >> 21;
    int s_ang = s;
    float* X = Xq;
    if (isK) {
        if (s >= cnt[b]) return;
        s_ang = cidx[b * Sz + s];
        X = Xk;
    }
    long base = ((long)(b * Sz + s)) * Dz + h * DHz + 2 * i;
    float c = cosb[s_ang * 64 + i], sn = sinb[s_ang * 64 + i];
    float x1 = X[base], x2 = X[base + 1];
    X[base]     = x1 * c - x2 * sn;
    X[base + 1] = x1 * sn + x2 * c;
}

// ---------------------------------------------------------------------------
// Flash attention over COMPACTED keys (fp32 SIMT).
// ---------------------------------------------------------------------------
#define FL_SMEM ((64*128 + 64*129 + 64*128 + 64*64) * 4)

__global__ __launch_bounds__(256) void flash_kernel(
    const float* __restrict__ Q, const float* __restrict__ K,
    const float* __restrict__ V, const int* __restrict__ cnt,
    float* __restrict__ O)
{
    extern __shared__ float sm[];
    float* sQ = sm;                 // 64 x 128
    float* sK = sQ + 64 * 128;      // 64 x 129
    float* sV = sK + 64 * 129;      // 64 x 128
    float* sS = sV + 64 * 128;      // 64 x 64

    const int tid = threadIdx.x;
    const int tx = tid & 15, ty = tid >> 4;
    const int blk = blockIdx.x;
    const int qt = blk & 31;
    const int h  = (blk >> 5) & 15;
    const int b  = blk >> 9;
    const int q0 = qt * 64;
    const float scale = 0.08838834764831845f;   // 1/sqrt(128)
    const int kmax = cnt[b];

#pragma unroll
    for (int r = 0; r < 32; r++) {
        int e = r * 256 + tid;
        int row = e >> 7, col = e & 127;
        sQ[row * 128 + col] = Q[((long)(b * Sz + q0 + row)) * Dz + h * DHz + col];
    }

    float m_i[4], l_i[4], o[4][8];
#pragma unroll
    for (int i = 0; i < 4; i++) {
        m_i[i] = -1e30f; l_i[i] = 0.f;
#pragma unroll
        for (int c = 0; c < 8; c++) o[i][c] = 0.f;
    }

    for (int k0 = 0; k0 < kmax; k0 += 64) {
        __syncthreads();
#pragma unroll
        for (int r = 0; r < 32; r++) {
            int e = r * 256 + tid;
            int row = e >> 7, col = e & 127;
            long gg = ((long)(b * Sz + k0 + row)) * Dz + h * DHz + col;
            sK[row * 129 + col] = K[gg];
            sV[row * 128 + col] = V[gg];
        }
        __syncthreads();

        float accs[4][4];
#pragma unroll
        for (int i = 0; i < 4; i++)
#pragma unroll
            for (int j = 0; j < 4; j++) accs[i][j] = 0.f;

#pragma unroll 4
        for (int k = 0; k < 128; k++) {
            float a[4], bb[4];
#pragma unroll
            for (int i = 0; i < 4; i++) a[i]  = sQ[(ty * 4 + i) * 128 + k];
#pragma unroll
            for (int j = 0; j < 4; j++) bb[j] = sK[(tx * 4 + j) * 129 + k];
#pragma unroll
            for (int i = 0; i < 4; i++)
#pragma unroll
                for (int j = 0; j < 4; j++) accs[i][j] += a[i] * bb[j];
        }

        float sv[4][4];
#pragma unroll
        for (int j = 0; j < 4; j++) {
            bool msk = (k0 + tx * 4 + j) >= kmax;
#pragma unroll
            for (int i = 0; i < 4; i++)
                sv[i][j] = msk ? -1e30f : accs[i][j] * scale;
        }

#pragma unroll
        for (int i = 0; i < 4; i++) {
            float tm = fmaxf(fmaxf(sv[i][0], sv[i][1]), fmaxf(sv[i][2], sv[i][3]));
#pragma unroll
            for (int d = 1; d < 16; d <<= 1)
                tm = fmaxf(tm, __shfl_xor_sync(0xffffffffu, tm, d));
            float nm = fmaxf(m_i[i], tm);
            float corr = __expf(m_i[i] - nm);
            float p[4], ps = 0.f;
#pragma unroll
            for (int j = 0; j < 4; j++) { p[j] = __expf(sv[i][j] - nm); ps += p[j]; }
#pragma unroll
            for (int d = 1; d < 16; d <<= 1)
                ps += __shfl_xor_sync(0xffffffffu, ps, d);
            l_i[i] = l_i[i] * corr + ps;
            m_i[i] = nm;
#pragma unroll
            for (int c = 0; c < 8; c++) o[i][c] *= corr;
#pragma unroll
            for (int j = 0; j < 4; j++)
                sS[(ty * 4 + i) * 64 + tx * 4 + j] = p[j];
        }
        __syncthreads();

#pragma unroll 4
        for (int kc = 0; kc < 64; kc++) {
            float4 v0 = *(const float4*)&sV[kc * 128 + tx * 8];
            float4 v1 = *(const float4*)&sV[kc * 128 + tx * 8 + 4];
#pragma unroll
            for (int i = 0; i < 4; i++) {
                float s = sS[(ty * 4 + i) * 64 + kc];
                o[i][0] += s * v0.x; o[i][1] += s * v0.y;
                o[i][2] += s * v0.z; o[i][3] += s * v0.w;
                o[i][4] += s * v1.x; o[i][5] += s * v1.y;
                o[i][6] += s * v1.z; o[i][7] += s * v1.w;
            }
        }
    }

#pragma unroll
    for (int i = 0; i < 4; i++) {
        float inv = 1.f / l_i[i];
        long base = ((long)(b * Sz + q0 + ty * 4 + i)) * Dz + h * DHz + tx * 8;
        float4 r0 = { o[i][0]*inv, o[i][1]*inv, o[i][2]*inv, o[i][3]*inv };
        float4 r1 = { o[i][4]*inv, o[i][5]*inv, o[i][6]*inv, o[i][7]*inv };
        *(float4*)&O[base]     = r0;
        *(float4*)&O[base + 4] = r1;
    }
}

// ---------------------------------------------------------------------------
// LayerNorm over last dim (2048), one CTA per row
// ---------------------------------------------------------------------------
__global__ __launch_bounds__(256) void ln_kernel(
    const float* __restrict__ X, const float* __restrict__ gamma,
    const float* __restrict__ beta, float* __restrict__ Y)
{
    const int row = blockIdx.x;
    const int tid = threadIdx.x;
    const float* x = X + (long)row * Dz;

    float v[8], s = 0.f, s2 = 0.f;
#pragma unroll
    for (int r = 0; r < 8; r++) {
        float t = x[r * 256 + tid];
        v[r] = t; s += t; s2 += t * t;
    }
#pragma unroll
    for (int d = 16; d >= 1; d >>= 1) {
        s  += __shfl_xor_sync(0xffffffffu, s,  d);
        s2 += __shfl_xor_sync(0xffffffffu, s2, d);
    }
    __shared__ float rs[8], rs2[8];
    __shared__ float s_mean, s_rstd;
    int wid = tid >> 5, lane = tid & 31;
    if (lane == 0) { rs[wid] = s; rs2[wid] = s2; }
    __syncthreads();
    if (tid == 0) {
        float S = 0.f, S2 = 0.f;
        for (int w = 0; w < 8; w++) { S += rs[w]; S2 += rs2[w]; }
        float mu = S * (1.f / 2048.f);
        float var = S2 * (1.f / 2048.f) - mu * mu;
        s_mean = mu;
        s_rstd = rsqrtf(var + 1e-5f);
    }
    __syncthreads();
    float mu = s_mean, rstd = s_rstd;
    float* y = Y + (long)row * Dz;
#pragma unroll
    for (int r = 0; r < 8; r++) {
        int c = r * 256 + tid;
        y[c] = (v[r] - mu) * rstd * gamma[c] + beta[c];
    }
}

// ---------------------------------------------------------------------------
extern "C" void kernel_launch(void* const* d_in, const int* in_sizes, int n_in,
                              void* d_out, int out_size)
{
    const float* q_input  = (const float*)d_in[0];
    const float* kv_input = (const float*)d_in[1];
    const int*   mask     = (const int*)d_in[2];    // bool -> int32 in harness
    const float* Wq = (const float*)d_in[3];
    const float* Wk = (const float*)d_in[4];
    const float* Wv = (const float*)d_in[5];
    const float* Wo = (const float*)d_in[6];
    const float* ln_gamma = (const float*)d_in[7];
    const float* ln_beta  = (const float*)d_in[8];
    const float* rope_cos = (const float*)d_in[9];
    const float* rope_sin = (const float*)d_in[10];
    float* out = (float*)d_out;

    float *pQ, *pK, *pV, *pA, *pR, *pKVc;
    int *pcidx, *pcnt;
    cudaGetSymbolAddress((void**)&pQ, g_Q);
    cudaGetSymbolAddress((void**)&pK, g_K);
    cudaGetSymbolAddress((void**)&pV, g_V);
    cudaGetSymbolAddress((void**)&pA, g_A);
    cudaGetSymbolAddress((void**)&pR, g_R);
    cudaGetSymbolAddress((void**)&pKVc, g_KVc);
    cudaGetSymbolAddress((void**)&pcidx, g_cidx);
    cudaGetSymbolAddress((void**)&pcnt, g_cnt);

    cudaFuncSetAttribute(flash_kernel,
                         cudaFuncAttributeMaxDynamicSharedMemorySize, FL_SMEM);

    const int M = Bz * Sz;   // 8192
    dim3 gq(16, 64, 1), gkv(16, 64, 2);

    // mask compaction + gather
    compact_kernel<<<Bz, 1024>>>(mask, pcidx, pcnt);
    gather_kernel<<<M, 256>>>(kv_input, pcidx, pcnt, pKVc);

    // projections (K/V on compacted rows, with early-exit)
    tgemm<<<gq, 256>>>(q_input, Wq, Wq, nullptr, pQ, pQ, nullptr);
    tgemm<<<gkv, 256>>>(pKVc, Wk, Wv, nullptr, pK, pV, pcnt);

    // RoPE (Q full; K compacted, angles from original positions)
    long rope_threads = 2L * Bz * Sz * NHz * 64;
    rope2_kernel<<<(int)(rope_threads / 256), 256>>>(pQ, pK, rope_cos, rope_sin,
                                                     pcidx, pcnt);

    // attention over compacted keys
    flash_kernel<<<Bz * NHz * (Sz / 64), 256, FL_SMEM>>>(pQ, pK, pV, pcnt, pA);

    // output projection + residual
    tgemm<<<gq, 256>>>(pA, Wo, Wo, q_input, pR, pR, nullptr);

    // LayerNorm
    ln_kernel<<<M, 256>>>(pR, ln_gamma, ln_beta, out);
}

// round 14
// speedup vs baseline: 4.4483x; 1.5625x over previous
#include <cuda_runtime.h>
#include <cuda_bf16.h>
#include <cstdint>
#include <math.h>

// Problem constants
#define Bz 4
#define Sz 2048
#define Dz 2048
#define NHz 16
#define DHz 128

#define TOT (4UL*2048UL*2048UL)   // B*S*D elements

// Scratch (allocation-free rule: __device__ globals)
__device__ float g_Q[TOT];
__device__ float g_K[TOT];
__device__ float g_V[TOT];
__device__ float g_A[TOT];
__device__ float g_R[TOT];
__device__ float g_KVc[TOT];      // compacted kv_input
__device__ int   g_cidx[Bz * Sz];
__device__ int   g_cnt[Bz];

// ===========================================================================
// tf32 helpers (base-family PTX, assembles for plain compute_103)
// ===========================================================================
__device__ __forceinline__ float tf32r(float x) {
    uint32_t u;
    asm("cvt.rna.tf32.f32 %0, %1;" : "=r"(u) : "f"(x));
    return __uint_as_float(u);
}
__device__ __forceinline__ void mma_tf32(float* c, const uint32_t* a, const uint32_t* b) {
    asm volatile(
        "mma.sync.aligned.m16n8k8.row.col.f32.tf32.tf32.f32 "
        "{%0,%1,%2,%3}, {%4,%5,%6,%7}, {%8,%9}, {%0,%1,%2,%3};"
        : "+f"(c[0]), "+f"(c[1]), "+f"(c[2]), "+f"(c[3])
        : "r"(a[0]), "r"(a[1]), "r"(a[2]), "r"(a[3]), "r"(b[0]), "r"(b[1]));
}

// ===========================================================================
// Mask compaction
// ===========================================================================
__global__ __launch_bounds__(1024) void compact_kernel(
    const int* __restrict__ mask, int* __restrict__ cidx, int* __restrict__ cnt)
{
    __shared__ int ssum[1024];
    const int b = blockIdx.x, t = threadIdx.x;
    const int* m = mask + b * Sz;
    int u0 = (m[2 * t] == 0) ? 1 : 0;
    int u1 = (m[2 * t + 1] == 0) ? 1 : 0;
    int pair = u0 + u1;
    ssum[t] = pair;
    __syncthreads();
#pragma unroll
    for (int d = 1; d < 1024; d <<= 1) {
        int v = (t >= d) ? ssum[t - d] : 0;
        __syncthreads();
        ssum[t] += v;
        __syncthreads();
    }
    int excl = ssum[t] - pair;
    if (u0) cidx[b * Sz + excl] = 2 * t;
    if (u1) cidx[b * Sz + excl + u0] = 2 * t + 1;
    if (t == 1023) cnt[b] = ssum[1023];
}

__global__ __launch_bounds__(256) void gather_kernel(
    const float* __restrict__ kv, const int* __restrict__ cidx,
    const int* __restrict__ cnt, float* __restrict__ out)
{
    const int row = blockIdx.x;              // 0..8191
    const int b = row >> 11, r = row & 2047;
    const int n = cnt[b];
    float4* dst = (float4*)(out + (long)row * Dz);
    if (r < n) {
        const float4* src = (const float4*)(kv + ((long)(b * Sz + cidx[b * Sz + r])) * Dz);
#pragma unroll 2
        for (int i = threadIdx.x; i < 512; i += 256) dst[i] = src[i];
    } else {
        float4 z = {0.f, 0.f, 0.f, 0.f};
#pragma unroll 2
        for (int i = threadIdx.x; i < 512; i += 256) dst[i] = z;
    }
}

// ===========================================================================
// tf32 GEMM with FRAGMENT-MAJOR smem (unchanged from R13)
// ===========================================================================
#define A_KB_STRIDE 1024
#define A_STAGE     2048
#define B_NT_STRIDE 66
#define B_KB_STRIDE (16 * B_NT_STRIDE)
#define B_STAGE     (2 * B_KB_STRIDE)

__global__ __launch_bounds__(256, 2) void tgemm(
    const float* __restrict__ A,
    const float* __restrict__ Bx, const float* __restrict__ By,
    const float* __restrict__ Res, float* __restrict__ Cx, float* __restrict__ Cy,
    const int* __restrict__ cnt)
{
    const float* __restrict__ B = blockIdx.z ? By : Bx;
    float* __restrict__ C = blockIdx.z ? Cy : Cx;

    const int m0 = blockIdx.y * 128, n0 = blockIdx.x * 128;
    if (cnt) {
        int b = m0 >> 11, local = m0 & 2047;
        if (local >= cnt[b]) return;
    }

    __shared__ float sAf[2][A_STAGE];
    __shared__ float sBf[2][B_STAGE];

    const int tid = threadIdx.x;
    const int lane = tid & 31, wid = tid >> 5;
    const int wm = wid >> 2, wn = wid & 3;

    const int rrA = tid >> 4, colA = tid & 15;
    const int kbA = colA >> 3, cA = colA & 7;
    const int constA = kbA * A_KB_STRIDE
                     + ((rrA & 7) * 4 + (cA & 3)) * 4
                     + (rrA >> 3) + 2 * (cA >> 2);
    const int nB = tid & 127, hiB = tid >> 7;
    const int ntB = nB >> 3, nnB = nB & 7;

    float acc[4][4][4];
#pragma unroll
    for (int mi = 0; mi < 4; mi++)
#pragma unroll
        for (int ni = 0; ni < 4; ni++)
#pragma unroll
            for (int e = 0; e < 4; e++) acc[mi][ni][e] = 0.f;

    float ra[8], rb[8];

    auto ldg = [&](int k0) {
#pragma unroll
        for (int r = 0; r < 8; r++)
            ra[r] = A[(long)(m0 + r * 16 + rrA) * 2048 + k0 + colA];
#pragma unroll
        for (int r = 0; r < 8; r++)
            rb[r] = B[(long)(k0 + r * 2 + hiB) * 2048 + n0 + nB];
    };
    auto sts = [&](int st) {
#pragma unroll
        for (int r = 0; r < 8; r++)
            sAf[st][constA + r * 128] = tf32r(ra[r]);
#pragma unroll
        for (int r = 0; r < 8; r++) {
            int k = r * 2 + hiB;
            int kb = k >> 3, kk = k & 7;
            int addr = kb * B_KB_STRIDE + ntB * B_NT_STRIDE
                     + (nnB * 4 + (kk & 3)) * 2 + (kk >> 2);
            sBf[st][addr] = tf32r(rb[r]);
        }
    };

    ldg(0);
    sts(0);
    __syncthreads();

    for (int c = 0; c < 128; c++) {
        const int st = c & 1;
        if (c + 1 < 128) ldg((c + 1) * 16);

#pragma unroll
        for (int kb = 0; kb < 2; kb++) {
            uint4 af[4];
            uint2 bf[4];
#pragma unroll
            for (int mi = 0; mi < 4; mi++)
                af[mi] = *(const uint4*)&sAf[st][kb * A_KB_STRIDE
                                                + (wm * 4 + mi) * 128 + lane * 4];
#pragma unroll
            for (int ni = 0; ni < 4; ni++)
                bf[ni] = *(const uint2*)&sBf[st][kb * B_KB_STRIDE
                                                + (wn * 4 + ni) * B_NT_STRIDE + lane * 2];
#pragma unroll
            for (int mi = 0; mi < 4; mi++)
#pragma unroll
                for (int ni = 0; ni < 4; ni++)
                    mma_tf32(acc[mi][ni], (const uint32_t*)&af[mi],
                             (const uint32_t*)&bf[ni]);
        }

        if (c + 1 < 128) {
            __syncthreads();
            sts((c + 1) & 1);
            __syncthreads();
        }
    }

    const int gg = lane >> 2, tt = lane & 3;
#pragma unroll
    for (int mi = 0; mi < 4; mi++) {
        int r0 = m0 + wm * 64 + mi * 16 + gg;
#pragma unroll
        for (int ni = 0; ni < 4; ni++) {
            int col = n0 + wn * 32 + ni * 8 + tt * 2;
            long o0 = (long)r0 * 2048 + col;
            long o1 = (long)(r0 + 8) * 2048 + col;
            float2 v0 = { acc[mi][ni][0], acc[mi][ni][1] };
            float2 v1 = { acc[mi][ni][2], acc[mi][ni][3] };
            if (Res) {
                float2 q0 = *(const float2*)&Res[o0];
                float2 q1 = *(const float2*)&Res[o1];
                v0.x += q0.x; v0.y += q0.y;
                v1.x += q1.x; v1.y += q1.y;
            }
            *(float2*)&C[o0] = v0;
            *(float2*)&C[o1] = v1;
        }
    }
}

// ---------------------------------------------------------------------------
// RoPE on Q (original order) and compacted K (angle from original position)
// ---------------------------------------------------------------------------
__global__ void rope2_kernel(float* __restrict__ Xq, float* __restrict__ Xk,
                             const float* __restrict__ cosb,
                             const float* __restrict__ sinb,
                             const int* __restrict__ cidx,
                             const int* __restrict__ cnt)
{
    long idx = (long)blockIdx.x * blockDim.x + threadIdx.x;  // 2 * 2^23
    int isK = (int)(idx >> 23);
    int t = (int)(idx & ((1 << 23) - 1));
    int i = t & 63;
    int h = (t >> 6) & 15;
    int s = (t >> 10) & 2047;
    int b = t >> 21;
    int s_ang = s;
    float* X = Xq;
    if (isK) {
        if (s >= cnt[b]) return;
        s_ang = cidx[b * Sz + s];
        X = Xk;
    }
    long base = ((long)(b * Sz + s)) * Dz + h * DHz + 2 * i;
    float c = cosb[s_ang * 64 + i], sn = sinb[s_ang * 64 + i];
    float x1 = X[base], x2 = X[base + 1];
    X[base]     = x1 * c - x2 * sn;
    X[base + 1] = x1 * sn + x2 * c;
}

// ===========================================================================
// Flash attention with tf32 mma, fragment-major smem, warp-local softmax.
// CTA = 128 q-rows x (b,h). 8 warps; warp w owns q-rows [w*16, w*16+16).
// Per 64-key tile:
//   S = Q@K^T : A = sQf (frag-major A map), B = sKf (n=key, k=d map)
//   softmax   : rows g / g+8 per thread; quad shfl reduce; online m,l
//   P -> sPf  : C-layout -> A-frag-major via two STS.64 per (ni)
//   O += P@V  : A = sPf, B = sVf (n=d, k=key map; implicit transpose)
// smem (floats): Q 16*1024 | K 16*528 | V 8*1056 | P 8*1024
// ===========================================================================
#define FQ_OFF 0
#define FK_OFF 16384
#define FV_OFF (16384 + 8448)
#define FP_OFF (16384 + 8448 + 8448)
#define FLM_FLOATS (16384 + 8448 + 8448 + 8192)      // 41472
#define FLM_SMEM (FLM_FLOATS * 4)                    // 165888 B

__global__ __launch_bounds__(256, 1) void flashmma_kernel(
    const float* __restrict__ Q, const float* __restrict__ K,
    const float* __restrict__ V, const int* __restrict__ cnt,
    float* __restrict__ O)
{
    extern __shared__ float sf[];
    float* sQf = sf + FQ_OFF;
    float* sKf = sf + FK_OFF;
    float* sVf = sf + FV_OFF;
    float* sPf = sf + FP_OFF;

    const int tid = threadIdx.x;
    const int lane = tid & 31, w = tid >> 5;
    const int g = lane >> 2, tig = lane & 3;
    const int blk = blockIdx.x;
    const int qt = blk & 15;
    const int h  = (blk >> 4) & 15;
    const int b  = blk >> 8;
    const int q0 = qt * 128;
    const int kmax = cnt[b];
    const float scale = 0.08838834764831845f;   // 1/sqrt(128)

    // ---- Q tile (128 x 128) -> A-fragment-major, tf32
    {
        const int rrA = tid >> 4, colA = tid & 15;
        const int c7 = colA & 7;
        const int laneA = (rrA & 7) * 4 + (c7 & 3);
        const int regA = (rrA >> 3) + 2 * (c7 >> 2);
        const long gb = ((long)(b * Sz + q0 + rrA)) * Dz + h * DHz + colA;
#pragma unroll
        for (int r8 = 0; r8 < 8; r8++)
#pragma unroll
            for (int cc = 0; cc < 8; cc++) {
                int kb = cc * 2 + (colA >> 3);
                float v = Q[gb + (long)(r8 * 16) * Dz + cc * 16];
                sQf[kb * 1024 + r8 * 128 + laneA * 4 + regA] = tf32r(v);
            }
    }

    float m_i[2] = {-1e30f, -1e30f};
    float l_i[2] = {0.f, 0.f};
    float oacc[16][4];
#pragma unroll
    for (int ni = 0; ni < 16; ni++)
#pragma unroll
        for (int e = 0; e < 4; e++) oacc[ni][e] = 0.f;

    // producer constants for K/V (same per-thread pattern)
    const int dL = tid & 127, hiL = tid >> 7;
    const int kbK = dL >> 3, kkK = dL & 7;                 // K: k = d
    const int ntV = dL >> 3, nnV = dL & 7;                 // V: n = d

    const int ntiles = (kmax + 63) >> 6;
    for (int t = 0; t < ntiles; t++) {
        const int k0 = t << 6;
        __syncthreads();   // protect sKf/sVf reuse (and Q visibility at t=0)

        // ---- K tile 64 keys x 128 d -> B-frag (n=key, k=d)
#pragma unroll 4
        for (int r = 0; r < 32; r++) {
            int key = r * 2 + hiL;
            long gk = ((long)(b * Sz + k0 + key)) * Dz + h * DHz + dL;
            float kv = K[gk];
            int nt = key >> 3, nn = key & 7;
            sKf[kbK * 528 + nt * 66 + (nn * 4 + (kkK & 3)) * 2 + (kkK >> 2)] = tf32r(kv);
            float vv = V[gk];
            int kb = key >> 3, kk = key & 7;
            sVf[kb * 1056 + ntV * 66 + (nnV * 4 + (kk & 3)) * 2 + (kk >> 2)] = tf32r(vv);
        }
        __syncthreads();

        // ---- S = Q @ K^T  (warp: 16 rows x 64 keys)
        float sacc[8][4];
#pragma unroll
        for (int ni = 0; ni < 8; ni++)
#pragma unroll
            for (int e = 0; e < 4; e++) sacc[ni][e] = 0.f;

#pragma unroll
        for (int kb = 0; kb < 16; kb++) {
            uint4 af = *(const uint4*)&sQf[kb * 1024 + w * 128 + lane * 4];
#pragma unroll
            for (int ni = 0; ni < 8; ni++) {
                uint2 bf = *(const uint2*)&sKf[kb * 528 + ni * 66 + lane * 2];
                mma_tf32(sacc[ni], (const uint32_t*)&af, (const uint32_t*)&bf);
            }
        }

        // ---- mask + scale; row maxima (rows g, g+8)
        float tm0 = -1e30f, tm1 = -1e30f;
#pragma unroll
        for (int ni = 0; ni < 8; ni++) {
            int key = k0 + ni * 8 + 2 * tig;
            bool ms0 = key >= kmax, ms1 = (key + 1) >= kmax;
            sacc[ni][0] = ms0 ? -1e30f : sacc[ni][0] * scale;
            sacc[ni][1] = ms1 ? -1e30f : sacc[ni][1] * scale;
            sacc[ni][2] = ms0 ? -1e30f : sacc[ni][2] * scale;
            sacc[ni][3] = ms1 ? -1e30f : sacc[ni][3] * scale;
            tm0 = fmaxf(tm0, fmaxf(sacc[ni][0], sacc[ni][1]));
            tm1 = fmaxf(tm1, fmaxf(sacc[ni][2], sacc[ni][3]));
        }
        tm0 = fmaxf(tm0, __shfl_xor_sync(0xffffffffu, tm0, 1));
        tm0 = fmaxf(tm0, __shfl_xor_sync(0xffffffffu, tm0, 2));
        tm1 = fmaxf(tm1, __shfl_xor_sync(0xffffffffu, tm1, 1));
        tm1 = fmaxf(tm1, __shfl_xor_sync(0xffffffffu, tm1, 2));

        float nm0 = fmaxf(m_i[0], tm0), nm1 = fmaxf(m_i[1], tm1);
        float corr0 = __expf(m_i[0] - nm0), corr1 = __expf(m_i[1] - nm1);

        // ---- exp, write P to A-frag-major smem, accumulate row sums
        float ps0 = 0.f, ps1 = 0.f;
        const int pbase = w * 128 + (g * 4 + ((2 * tig) & 3)) * 4 + 2 * (tig >> 1);
#pragma unroll
        for (int ni = 0; ni < 8; ni++) {
            float p0 = __expf(sacc[ni][0] - nm0);
            float p1 = __expf(sacc[ni][1] - nm0);
            float p2 = __expf(sacc[ni][2] - nm1);
            float p3 = __expf(sacc[ni][3] - nm1);
            ps0 += p0 + p1;
            ps1 += p2 + p3;
            float2 w0 = { tf32r(p0), tf32r(p2) };
            float2 w1 = { tf32r(p1), tf32r(p3) };
            *(float2*)&sPf[ni * 1024 + pbase]     = w0;
            *(float2*)&sPf[ni * 1024 + pbase + 4] = w1;
        }
        ps0 += __shfl_xor_sync(0xffffffffu, ps0, 1);
        ps0 += __shfl_xor_sync(0xffffffffu, ps0, 2);
        ps1 += __shfl_xor_sync(0xffffffffu, ps1, 1);
        ps1 += __shfl_xor_sync(0xffffffffu, ps1, 2);
        l_i[0] = l_i[0] * corr0 + ps0;  m_i[0] = nm0;
        l_i[1] = l_i[1] * corr1 + ps1;  m_i[1] = nm1;

        // rescale O accumulators
#pragma unroll
        for (int ni = 0; ni < 16; ni++) {
            oacc[ni][0] *= corr0; oacc[ni][1] *= corr0;
            oacc[ni][2] *= corr1; oacc[ni][3] *= corr1;
        }
        __syncwarp();   // sPf is warp-private; order STS before LDS

        // ---- O += P @ V  (warp: 16 rows x 128 d)
#pragma unroll
        for (int kb = 0; kb < 8; kb++) {
            uint4 af = *(const uint4*)&sPf[kb * 1024 + w * 128 + lane * 4];
#pragma unroll
            for (int ni = 0; ni < 16; ni++) {
                uint2 bf = *(const uint2*)&sVf[kb * 1056 + ni * 66 + lane * 2];
                mma_tf32(oacc[ni], (const uint32_t*)&af, (const uint32_t*)&bf);
            }
        }
        __syncwarp();   // PV reads done before next tile overwrites sPf
    }

    // ---- epilogue: normalize, store
    float inv0 = 1.f / l_i[0], inv1 = 1.f / l_i[1];
    int row0 = q0 + w * 16 + g;
#pragma unroll
    for (int ni = 0; ni < 16; ni++) {
        int col = h * DHz + ni * 8 + tig * 2;
        long o0 = ((long)(b * Sz + row0)) * Dz + col;
        long o1 = ((long)(b * Sz + row0 + 8)) * Dz + col;
        float2 v0 = { oacc[ni][0] * inv0, oacc[ni][1] * inv0 };
        float2 v1 = { oacc[ni][2] * inv1, oacc[ni][3] * inv1 };
        *(float2*)&O[o0] = v0;
        *(float2*)&O[o1] = v1;
    }
}

// ---------------------------------------------------------------------------
// LayerNorm over last dim (2048), one CTA per row
// ---------------------------------------------------------------------------
__global__ __launch_bounds__(256) void ln_kernel(
    const float* __restrict__ X, const float* __restrict__ gamma,
    const float* __restrict__ beta, float* __restrict__ Y)
{
    const int row = blockIdx.x;
    const int tid = threadIdx.x;
    const float* x = X + (long)row * Dz;

    float v[8], s = 0.f, s2 = 0.f;
#pragma unroll
    for (int r = 0; r < 8; r++) {
        float t = x[r * 256 + tid];
        v[r] = t; s += t; s2 += t * t;
    }
#pragma unroll
    for (int d = 16; d >= 1; d >>= 1) {
        s  += __shfl_xor_sync(0xffffffffu, s,  d);
        s2 += __shfl_xor_sync(0xffffffffu, s2, d);
    }
    __shared__ float rs[8], rs2[8];
    __shared__ float s_mean, s_rstd;
    int wid = tid >> 5, lane = tid & 31;
    if (lane == 0) { rs[wid] = s; rs2[wid] = s2; }
    __syncthreads();
    if (tid == 0) {
        float S = 0.f, S2 = 0.f;
        for (int w = 0; w < 8; w++) { S += rs[w]; S2 += rs2[w]; }
        float mu = S * (1.f / 2048.f);
        float var = S2 * (1.f / 2048.f) - mu * mu;
        s_mean = mu;
        s_rstd = rsqrtf(var + 1e-5f);
    }
    __syncthreads();
    float mu = s_mean, rstd = s_rstd;
    float* y = Y + (long)row * Dz;
#pragma unroll
    for (int r = 0; r < 8; r++) {
        int c = r * 256 + tid;
        y[c] = (v[r] - mu) * rstd * gamma[c] + beta[c];
    }
}

// ---------------------------------------------------------------------------
extern "C" void kernel_launch(void* const* d_in, const int* in_sizes, int n_in,
                              void* d_out, int out_size)
{
    const float* q_input  = (const float*)d_in[0];
    const float* kv_input = (const float*)d_in[1];
    const int*   mask     = (const int*)d_in[2];    // bool -> int32 in harness
    const float* Wq = (const float*)d_in[3];
    const float* Wk = (const float*)d_in[4];
    const float* Wv = (const float*)d_in[5];
    const float* Wo = (const float*)d_in[6];
    const float* ln_gamma = (const float*)d_in[7];
    const float* ln_beta  = (const float*)d_in[8];
    const float* rope_cos = (const float*)d_in[9];
    const float* rope_sin = (const float*)d_in[10];
    float* out = (float*)d_out;

    float *pQ, *pK, *pV, *pA, *pR, *pKVc;
    int *pcidx, *pcnt;
    cudaGetSymbolAddress((void**)&pQ, g_Q);
    cudaGetSymbolAddress((void**)&pK, g_K);
    cudaGetSymbolAddress((void**)&pV, g_V);
    cudaGetSymbolAddress((void**)&pA, g_A);
    cudaGetSymbolAddress((void**)&pR, g_R);
    cudaGetSymbolAddress((void**)&pKVc, g_KVc);
    cudaGetSymbolAddress((void**)&pcidx, g_cidx);
    cudaGetSymbolAddress((void**)&pcnt, g_cnt);

    cudaFuncSetAttribute(flashmma_kernel,
                         cudaFuncAttributeMaxDynamicSharedMemorySize, FLM_SMEM);

    const int M = Bz * Sz;   // 8192
    dim3 gq(16, 64, 1), gkv(16, 64, 2);

    // mask compaction + gather
    compact_kernel<<<Bz, 1024>>>(mask, pcidx, pcnt);
    gather_kernel<<<M, 256>>>(kv_input, pcidx, pcnt, pKVc);

    // projections (K/V on compacted rows, with early-exit)
    tgemm<<<gq, 256>>>(q_input, Wq, Wq, nullptr, pQ, pQ, nullptr);
    tgemm<<<gkv, 256>>>(pKVc, Wk, Wv, nullptr, pK, pV, pcnt);

    // RoPE (Q full; K compacted, angles from original positions)
    long rope_threads = 2L * Bz * Sz * NHz * 64;
    rope2_kernel<<<(int)(rope_threads / 256), 256>>>(pQ, pK, rope_cos, rope_sin,
                                                     pcidx, pcnt);

    // attention over compacted keys (tf32 mma flash)
    flashmma_kernel<<<Bz * NHz * (Sz / 128), 256, FLM_SMEM>>>(pQ, pK, pV, pcnt, pA);

    // output projection + residual
    tgemm<<<gq, 256>>>(pA, Wo, Wo, q_input, pR, pR, nullptr);

    // LayerNorm
    ln_kernel<<<M, 256>>>(pR, ln_gamma, ln_beta, out);
}

// round 15
// speedup vs baseline: 5.0466x; 1.1345x over previous
#include <cuda_runtime.h>
#include <cuda_bf16.h>
#include <cstdint>
#include <math.h>

// Problem constants
#define Bz 4
#define Sz 2048
#define Dz 2048
#define NHz 16
#define DHz 128

#define TOT (4UL*2048UL*2048UL)   // B*S*D elements

// Scratch (allocation-free rule: __device__ globals)
__device__ float g_Q[TOT];
__device__ float g_K[TOT];
__device__ float g_V[TOT];
__device__ float g_A[TOT];
__device__ float g_R[TOT];
__device__ float g_KVc[TOT];      // compacted kv_input
__device__ int   g_cidx[Bz * Sz];
__device__ int   g_cnt[Bz];

// ===========================================================================
// tf32 helpers (base-family PTX, assembles for plain compute_103)
// ===========================================================================
__device__ __forceinline__ float tf32r(float x) {
    uint32_t u;
    asm("cvt.rna.tf32.f32 %0, %1;" : "=r"(u) : "f"(x));
    return __uint_as_float(u);
}
__device__ __forceinline__ void mma_tf32(float* c, const uint32_t* a, const uint32_t* b) {
    asm volatile(
        "mma.sync.aligned.m16n8k8.row.col.f32.tf32.tf32.f32 "
        "{%0,%1,%2,%3}, {%4,%5,%6,%7}, {%8,%9}, {%0,%1,%2,%3};"
        : "+f"(c[0]), "+f"(c[1]), "+f"(c[2]), "+f"(c[3])
        : "r"(a[0]), "r"(a[1]), "r"(a[2]), "r"(a[3]), "r"(b[0]), "r"(b[1]));
}

// ===========================================================================
// Mask compaction
// ===========================================================================
__global__ __launch_bounds__(1024) void compact_kernel(
    const int* __restrict__ mask, int* __restrict__ cidx, int* __restrict__ cnt)
{
    __shared__ int ssum[1024];
    const int b = blockIdx.x, t = threadIdx.x;
    const int* m = mask + b * Sz;
    int u0 = (m[2 * t] == 0) ? 1 : 0;
    int u1 = (m[2 * t + 1] == 0) ? 1 : 0;
    int pair = u0 + u1;
    ssum[t] = pair;
    __syncthreads();
#pragma unroll
    for (int d = 1; d < 1024; d <<= 1) {
        int v = (t >= d) ? ssum[t - d] : 0;
        __syncthreads();
        ssum[t] += v;
        __syncthreads();
    }
    int excl = ssum[t] - pair;
    if (u0) cidx[b * Sz + excl] = 2 * t;
    if (u1) cidx[b * Sz + excl + u0] = 2 * t + 1;
    if (t == 1023) cnt[b] = ssum[1023];
}

__global__ __launch_bounds__(256) void gather_kernel(
    const float* __restrict__ kv, const int* __restrict__ cidx,
    const int* __restrict__ cnt, float* __restrict__ out)
{
    const int row = blockIdx.x;              // 0..8191
    const int b = row >> 11, r = row & 2047;
    const int n = cnt[b];
    float4* dst = (float4*)(out + (long)row * Dz);
    if (r < n) {
        const float4* src = (const float4*)(kv + ((long)(b * Sz + cidx[b * Sz + r])) * Dz);
#pragma unroll 2
        for (int i = threadIdx.x; i < 512; i += 256) dst[i] = src[i];
    } else {
        float4 z = {0.f, 0.f, 0.f, 0.f};
#pragma unroll 2
        for (int i = threadIdx.x; i < 512; i += 256) dst[i] = z;
    }
}

// ===========================================================================
// tf32 GEMM, fragment-major smem, double-buffered with ONE barrier per chunk
// ===========================================================================
#define A_KB_STRIDE 1024
#define A_STAGE     2048
#define B_NT_STRIDE 66
#define B_KB_STRIDE (16 * B_NT_STRIDE)
#define B_STAGE     (2 * B_KB_STRIDE)

__global__ __launch_bounds__(256, 2) void tgemm(
    const float* __restrict__ A,
    const float* __restrict__ Bx, const float* __restrict__ By,
    const float* __restrict__ Res, float* __restrict__ Cx, float* __restrict__ Cy,
    const int* __restrict__ cnt)
{
    const float* __restrict__ B = blockIdx.z ? By : Bx;
    float* __restrict__ C = blockIdx.z ? Cy : Cx;

    const int m0 = blockIdx.y * 128, n0 = blockIdx.x * 128;
    if (cnt) {
        int b = m0 >> 11, local = m0 & 2047;
        if (local >= cnt[b]) return;
    }

    __shared__ float sAf[2][A_STAGE];
    __shared__ float sBf[2][B_STAGE];

    const int tid = threadIdx.x;
    const int lane = tid & 31, wid = tid >> 5;
    const int wm = wid >> 2, wn = wid & 3;

    const int rrA = tid >> 4, colA = tid & 15;
    const int kbA = colA >> 3, cA = colA & 7;
    const int constA = kbA * A_KB_STRIDE
                     + ((rrA & 7) * 4 + (cA & 3)) * 4
                     + (rrA >> 3) + 2 * (cA >> 2);
    const int nB = tid & 127, hiB = tid >> 7;
    const int ntB = nB >> 3, nnB = nB & 7;

    float acc[4][4][4];
#pragma unroll
    for (int mi = 0; mi < 4; mi++)
#pragma unroll
        for (int ni = 0; ni < 4; ni++)
#pragma unroll
            for (int e = 0; e < 4; e++) acc[mi][ni][e] = 0.f;

    float ra[8], rb[8];

    auto ldg = [&](int k0) {
#pragma unroll
        for (int r = 0; r < 8; r++)
            ra[r] = A[(long)(m0 + r * 16 + rrA) * 2048 + k0 + colA];
#pragma unroll
        for (int r = 0; r < 8; r++)
            rb[r] = B[(long)(k0 + r * 2 + hiB) * 2048 + n0 + nB];
    };
    auto sts = [&](int st) {
#pragma unroll
        for (int r = 0; r < 8; r++)
            sAf[st][constA + r * 128] = tf32r(ra[r]);
#pragma unroll
        for (int r = 0; r < 8; r++) {
            int k = r * 2 + hiB;
            int kb = k >> 3, kk = k & 7;
            int addr = kb * B_KB_STRIDE + ntB * B_NT_STRIDE
                     + (nnB * 4 + (kk & 3)) * 2 + (kk >> 2);
            sBf[st][addr] = tf32r(rb[r]);
        }
    };

    ldg(0);
    sts(0);
    __syncthreads();

    for (int c = 0; c < 128; c++) {
        const int st = c & 1;
        if (c + 1 < 128) ldg((c + 1) * 16);

#pragma unroll
        for (int kb = 0; kb < 2; kb++) {
            uint4 af[4];
            uint2 bf[4];
#pragma unroll
            for (int mi = 0; mi < 4; mi++)
                af[mi] = *(const uint4*)&sAf[st][kb * A_KB_STRIDE
                                                + (wm * 4 + mi) * 128 + lane * 4];
#pragma unroll
            for (int ni = 0; ni < 4; ni++)
                bf[ni] = *(const uint2*)&sBf[st][kb * B_KB_STRIDE
                                                + (wn * 4 + ni) * B_NT_STRIDE + lane * 2];
#pragma unroll
            for (int mi = 0; mi < 4; mi++)
#pragma unroll
                for (int ni = 0; ni < 4; ni++)
                    mma_tf32(acc[mi][ni], (const uint32_t*)&af[mi],
                             (const uint32_t*)&bf[ni]);
        }

        if (c + 1 < 128) {
            // Write next chunk into the other stage. The barrier at the end of
            // the previous iteration guarantees every warp is done reading it.
            sts((c + 1) & 1);
            __syncthreads();
        }
    }

    const int gg = lane >> 2, tt = lane & 3;
#pragma unroll
    for (int mi = 0; mi < 4; mi++) {
        int r0 = m0 + wm * 64 + mi * 16 + gg;
#pragma unroll
        for (int ni = 0; ni < 4; ni++) {
            int col = n0 + wn * 32 + ni * 8 + tt * 2;
            long o0 = (long)r0 * 2048 + col;
            long o1 = (long)(r0 + 8) * 2048 + col;
            float2 v0 = { acc[mi][ni][0], acc[mi][ni][1] };
            float2 v1 = { acc[mi][ni][2], acc[mi][ni][3] };
            if (Res) {
                float2 q0 = *(const float2*)&Res[o0];
                float2 q1 = *(const float2*)&Res[o1];
                v0.x += q0.x; v0.y += q0.y;
                v1.x += q1.x; v1.y += q1.y;
            }
            *(float2*)&C[o0] = v0;
            *(float2*)&C[o1] = v1;
        }
    }
}

// ---------------------------------------------------------------------------
// RoPE on Q (original order) and compacted K (angle from original position)
// ---------------------------------------------------------------------------
__global__ void rope2_kernel(float* __restrict__ Xq, float* __restrict__ Xk,
                             const float* __restrict__ cosb,
                             const float* __restrict__ sinb,
                             const int* __restrict__ cidx,
                             const int* __restrict__ cnt)
{
    long idx = (long)blockIdx.x * blockDim.x + threadIdx.x;  // 2 * 2^23
    int isK = (int)(idx >> 23);
    int t = (int)(idx & ((1 << 23) - 1));
    int i = t & 63;
    int h = (t >> 6) & 15;
    int s = (t >> 10) & 2047;
    int b = t >> 21;
    int s_ang = s;
    float* X = Xq;
    if (isK) {
        if (s >= cnt[b]) return;
        s_ang = cidx[b * Sz + s];
        X = Xk;
    }
    long base = ((long)(b * Sz + s)) * Dz + h * DHz + 2 * i;
    float c = cosb[s_ang * 64 + i], sn = sinb[s_ang * 64 + i];
    float x1 = X[base], x2 = X[base + 1];
    X[base]     = x1 * c - x2 * sn;
    X[base + 1] = x1 * sn + x2 * c;
}

// ===========================================================================
// Flash attention, tf32 mma, 64 q-rows per CTA (128 threads, 4 warps),
// P aliases K region (K dead after S-phase; extra __syncthreads makes it safe).
// smem/CTA = 100352 B -> 2 CTAs/SM for latency hiding.
//   Q frag: [kb(16)*512 + sub(=warp)*128 + lane*4 + reg]          8192 f
//   K frag: [nt(8)*1056 + kb(16)*66 + (nn*4+(kk&3))*2 + (kk>>2)]  8448 f (|| P)
//   P frag: [kb(8)*512 + w*128 + lane*4 + reg]  (alias K)         4096 f
//   V frag: [kb(8)*1056 + nt(16)*66 + (nn*4+(kk&3))*2 + (kk>>2)]  8448 f
// Producer: warp = one key per iter, lane loads float4 (coalesced 512B);
// K stores provably conflict-free (bank == lane), V stores 2-way.
// ===========================================================================
#define FKP_OFF 8192
#define FV_OFF  (8192 + 8448)
#define FLM_FLOATS (8192 + 8448 + 8448)   // 25088
#define FLM_SMEM (FLM_FLOATS * 4)         // 100352 B

__global__ __launch_bounds__(128) void flashmma_kernel(
    const float* __restrict__ Q, const float* __restrict__ K,
    const float* __restrict__ V, const int* __restrict__ cnt,
    float* __restrict__ O)
{
    extern __shared__ float sf[];
    float* sQf = sf;
    float* sKf = sf + FKP_OFF;
    float* sPf = sf + FKP_OFF;   // alias: P overwrites K after S-phase
    float* sVf = sf + FV_OFF;

    const int tid = threadIdx.x;
    const int lane = tid & 31, w = tid >> 5;      // 4 warps
    const int g = lane >> 2, tig = lane & 3;
    const int blk = blockIdx.x;
    const int qt = blk & 31;
    const int h  = (blk >> 5) & 15;
    const int b  = blk >> 9;
    const int q0 = qt * 64;
    const int kmax = cnt[b];
    const float scale = 0.08838834764831845f;   // 1/sqrt(128)

    // ---- Q tile (64 x 128) -> A-fragment-major, tf32
    for (int idx = tid; idx < 64 * 128; idx += 128) {
        int row = idx >> 7, d = idx & 127;
        int sub = row >> 4, rr = row & 15, kb = d >> 3, c = d & 7;
        float v = Q[((long)(b * Sz + q0 + row)) * Dz + h * DHz + d];
        sQf[kb * 512 + sub * 128 + ((rr & 7) * 4 + (c & 3)) * 4
            + (rr >> 3) + 2 * (c >> 2)] = tf32r(v);
    }

    float m_i[2] = {-1e30f, -1e30f};
    float l_i[2] = {0.f, 0.f};
    float oacc[16][4];
#pragma unroll
    for (int ni = 0; ni < 16; ni++)
#pragma unroll
        for (int e = 0; e < 4; e++) oacc[ni][e] = 0.f;

    const int l2 = lane >> 1, l1 = lane & 1;

    const int ntiles = (kmax + 63) >> 6;
    for (int t = 0; t < ntiles; t++) {
        const int k0 = t << 6;
        __syncthreads();   // prev tile's P/V reads done (and Q visible at t=0)

        // ---- K/V producer: warp w handles keys w*16 .. w*16+15
#pragma unroll 4
        for (int i = 0; i < 16; i++) {
            int key = w * 16 + i;
            long gk = ((long)(b * Sz + k0 + key)) * Dz + h * DHz + lane * 4;
            float4 kq = *(const float4*)&K[gk];
            float4 vq = *(const float4*)&V[gk];
            // K: n = key, k = d
            int ntK = key >> 3, nnK = key & 7;
            int baseK = ntK * 1056 + l2 * 66 + nnK * 8 + l1;
            sKf[baseK + 0] = tf32r(kq.x);
            sKf[baseK + 2] = tf32r(kq.y);
            sKf[baseK + 4] = tf32r(kq.z);
            sKf[baseK + 6] = tf32r(kq.w);
            // V: n = d, k = key
            int kbV = key >> 3, kkV = key & 7;
            int baseV = kbV * 1056 + l2 * 66 + l1 * 32 + (kkV & 3) * 2 + (kkV >> 2);
            sVf[baseV + 0]  = tf32r(vq.x);
            sVf[baseV + 8]  = tf32r(vq.y);
            sVf[baseV + 16] = tf32r(vq.z);
            sVf[baseV + 24] = tf32r(vq.w);
        }
        __syncthreads();

        // ---- S = Q @ K^T  (warp: 16 rows x 64 keys)
        float sacc[8][4];
#pragma unroll
        for (int ni = 0; ni < 8; ni++)
#pragma unroll
            for (int e = 0; e < 4; e++) sacc[ni][e] = 0.f;

#pragma unroll
        for (int kb = 0; kb < 16; kb++) {
            uint4 af = *(const uint4*)&sQf[kb * 512 + w * 128 + lane * 4];
#pragma unroll
            for (int ni = 0; ni < 8; ni++) {
                uint2 bf = *(const uint2*)&sKf[ni * 1056 + kb * 66 + lane * 2];
                mma_tf32(sacc[ni], (const uint32_t*)&af, (const uint32_t*)&bf);
            }
        }
        __syncthreads();   // ALL warps done reading K before P overwrites it

        // ---- mask + scale; row maxima (rows g, g+8)
        float tm0 = -1e30f, tm1 = -1e30f;
#pragma unroll
        for (int ni = 0; ni < 8; ni++) {
            int key = k0 + ni * 8 + 2 * tig;
            bool ms0 = key >= kmax, ms1 = (key + 1) >= kmax;
            sacc[ni][0] = ms0 ? -1e30f : sacc[ni][0] * scale;
            sacc[ni][1] = ms1 ? -1e30f : sacc[ni][1] * scale;
            sacc[ni][2] = ms0 ? -1e30f : sacc[ni][2] * scale;
            sacc[ni][3] = ms1 ? -1e30f : sacc[ni][3] * scale;
            tm0 = fmaxf(tm0, fmaxf(sacc[ni][0], sacc[ni][1]));
            tm1 = fmaxf(tm1, fmaxf(sacc[ni][2], sacc[ni][3]));
        }
        tm0 = fmaxf(tm0, __shfl_xor_sync(0xffffffffu, tm0, 1));
        tm0 = fmaxf(tm0, __shfl_xor_sync(0xffffffffu, tm0, 2));
        tm1 = fmaxf(tm1, __shfl_xor_sync(0xffffffffu, tm1, 1));
        tm1 = fmaxf(tm1, __shfl_xor_sync(0xffffffffu, tm1, 2));

        float nm0 = fmaxf(m_i[0], tm0), nm1 = fmaxf(m_i[1], tm1);
        float corr0 = __expf(m_i[0] - nm0), corr1 = __expf(m_i[1] - nm1);

        // ---- exp, write P (A-frag-major, aliasing K), accumulate row sums
        float ps0 = 0.f, ps1 = 0.f;
        const int pbase = w * 128 + (g * 4 + ((2 * tig) & 3)) * 4 + 2 * (tig >> 1);
#pragma unroll
        for (int ni = 0; ni < 8; ni++) {
            float p0 = __expf(sacc[ni][0] - nm0);
            float p1 = __expf(sacc[ni][1] - nm0);
            float p2 = __expf(sacc[ni][2] - nm1);
            float p3 = __expf(sacc[ni][3] - nm1);
            ps0 += p0 + p1;
            ps1 += p2 + p3;
            float2 w0 = { tf32r(p0), tf32r(p2) };
            float2 w1 = { tf32r(p1), tf32r(p3) };
            *(float2*)&sPf[ni * 512 + pbase]     = w0;
            *(float2*)&sPf[ni * 512 + pbase + 4] = w1;
        }
        ps0 += __shfl_xor_sync(0xffffffffu, ps0, 1);
        ps0 += __shfl_xor_sync(0xffffffffu, ps0, 2);
        ps1 += __shfl_xor_sync(0xffffffffu, ps1, 1);
        ps1 += __shfl_xor_sync(0xffffffffu, ps1, 2);
        l_i[0] = l_i[0] * corr0 + ps0;  m_i[0] = nm0;
        l_i[1] = l_i[1] * corr1 + ps1;  m_i[1] = nm1;

#pragma unroll
        for (int ni = 0; ni < 16; ni++) {
            oacc[ni][0] *= corr0; oacc[ni][1] *= corr0;
            oacc[ni][2] *= corr1; oacc[ni][3] *= corr1;
        }
        __syncwarp();   // P region is warp-private: order STS before LDS

        // ---- O += P @ V  (warp: 16 rows x 128 d)
#pragma unroll
        for (int kb = 0; kb < 8; kb++) {
            uint4 af = *(const uint4*)&sPf[kb * 512 + w * 128 + lane * 4];
#pragma unroll
            for (int ni = 0; ni < 16; ni++) {
                uint2 bf = *(const uint2*)&sVf[kb * 1056 + ni * 66 + lane * 2];
                mma_tf32(oacc[ni], (const uint32_t*)&af, (const uint32_t*)&bf);
            }
        }
    }

    // ---- epilogue: normalize, store
    float inv0 = 1.f / l_i[0], inv1 = 1.f / l_i[1];
    int row0 = q0 + w * 16 + g;
#pragma unroll
    for (int ni = 0; ni < 16; ni++) {
        int col = h * DHz + ni * 8 + tig * 2;
        long o0 = ((long)(b * Sz + row0)) * Dz + col;
        long o1 = ((long)(b * Sz + row0 + 8)) * Dz + col;
        float2 v0 = { oacc[ni][0] * inv0, oacc[ni][1] * inv0 };
        float2 v1 = { oacc[ni][2] * inv1, oacc[ni][3] * inv1 };
        *(float2*)&O[o0] = v0;
        *(float2*)&O[o1] = v1;
    }
}

// ---------------------------------------------------------------------------
// LayerNorm over last dim (2048), one CTA per row
// ---------------------------------------------------------------------------
__global__ __launch_bounds__(256) void ln_kernel(
    const float* __restrict__ X, const float* __restrict__ gamma,
    const float* __restrict__ beta, float* __restrict__ Y)
{
    const int row = blockIdx.x;
    const int tid = threadIdx.x;
    const float* x = X + (long)row * Dz;

    float v[8], s = 0.f, s2 = 0.f;
#pragma unroll
    for (int r = 0; r < 8; r++) {
        float t = x[r * 256 + tid];
        v[r] = t; s += t; s2 += t * t;
    }
#pragma unroll
    for (int d = 16; d >= 1; d >>= 1) {
        s  += __shfl_xor_sync(0xffffffffu, s,  d);
        s2 += __shfl_xor_sync(0xffffffffu, s2, d);
    }
    __shared__ float rs[8], rs2[8];
    __shared__ float s_mean, s_rstd;
    int wid = tid >> 5, lane = tid & 31;
    if (lane == 0) { rs[wid] = s; rs2[wid] = s2; }
    __syncthreads();
    if (tid == 0) {
        float S = 0.f, S2 = 0.f;
        for (int w = 0; w < 8; w++) { S += rs[w]; S2 += rs2[w]; }
        float mu = S * (1.f / 2048.f);
        float var = S2 * (1.f / 2048.f) - mu * mu;
        s_mean = mu;
        s_rstd = rsqrtf(var + 1e-5f);
    }
    __syncthreads();
    float mu = s_mean, rstd = s_rstd;
    float* y = Y + (long)row * Dz;
#pragma unroll
    for (int r = 0; r < 8; r++) {
        int c = r * 256 + tid;
        y[c] = (v[r] - mu) * rstd * gamma[c] + beta[c];
    }
}

// ---------------------------------------------------------------------------
extern "C" void kernel_launch(void* const* d_in, const int* in_sizes, int n_in,
                              void* d_out, int out_size)
{
    const float* q_input  = (const float*)d_in[0];
    const float* kv_input = (const float*)d_in[1];
    const int*   mask     = (const int*)d_in[2];    // bool -> int32 in harness
    const float* Wq = (const float*)d_in[3];
    const float* Wk = (const float*)d_in[4];
    const float* Wv = (const float*)d_in[5];
    const float* Wo = (const float*)d_in[6];
    const float* ln_gamma = (const float*)d_in[7];
    const float* ln_beta  = (const float*)d_in[8];
    const float* rope_cos = (const float*)d_in[9];
    const float* rope_sin = (const float*)d_in[10];
    float* out = (float*)d_out;

    float *pQ, *pK, *pV, *pA, *pR, *pKVc;
    int *pcidx, *pcnt;
    cudaGetSymbolAddress((void**)&pQ, g_Q);
    cudaGetSymbolAddress((void**)&pK, g_K);
    cudaGetSymbolAddress((void**)&pV, g_V);
    cudaGetSymbolAddress((void**)&pA, g_A);
    cudaGetSymbolAddress((void**)&pR, g_R);
    cudaGetSymbolAddress((void**)&pKVc, g_KVc);
    cudaGetSymbolAddress((void**)&pcidx, g_cidx);
    cudaGetSymbolAddress((void**)&pcnt, g_cnt);

    cudaFuncSetAttribute(flashmma_kernel,
                         cudaFuncAttributeMaxDynamicSharedMemorySize, FLM_SMEM);

    const int M = Bz * Sz;   // 8192
    dim3 gq(16, 64, 1), gkv(16, 64, 2);

    // mask compaction + gather
    compact_kernel<<<Bz, 1024>>>(mask, pcidx, pcnt);
    gather_kernel<<<M, 256>>>(kv_input, pcidx, pcnt, pKVc);

    // projections (K/V on compacted rows, with early-exit)
    tgemm<<<gq, 256>>>(q_input, Wq, Wq, nullptr, pQ, pQ, nullptr);
    tgemm<<<gkv, 256>>>(pKVc, Wk, Wv, nullptr, pK, pV, pcnt);

    // RoPE (Q full; K compacted, angles from original positions)
    long rope_threads = 2L * Bz * Sz * NHz * 64;
    rope2_kernel<<<(int)(rope_threads / 256), 256>>>(pQ, pK, rope_cos, rope_sin,
                                                     pcidx, pcnt);

    // attention over compacted keys (tf32 mma flash, 64-row CTAs, 2/SM)
    flashmma_kernel<<<Bz * NHz * (Sz / 64), 128, FLM_SMEM>>>(pQ, pK, pV, pcnt, pA);

    // output projection + residual
    tgemm<<<gq, 256>>>(pA, Wo, Wo, q_input, pR, pR, nullptr);

    // LayerNorm
    ln_kernel<<<M, 256>>>(pR, ln_gamma, ln_beta, out);
}